// round 13
// baseline (speedup 1.0000x reference)
#include <cuda_runtime.h>
#include <math.h>

#define Bv 256
#define Tv 256
#define STOCHv 32
#define DETERv 512
#define HIDv 512
#define OBSv 18
#define ACTv 4
#define GATESv 1536
#define OUTCv 1216
#define NB 256

__device__ float g_xcat[Bv * 1024];        // [b][0:512]=h(t), [512:1024]=deter_in(t)
__device__ float g_gates[8][Bv * GATESv];  // gates split-K partials
__device__ float g_mm[2][8][Bv * HIDv];    // mm split-K partials
__device__ float g_deter[Bv * DETERv];
__device__ float g_init[DETERv + STOCHv];  // deter0, init_mean
__device__ unsigned g_bar_count;
__device__ unsigned g_bar_gen;

typedef unsigned long long u64;

static __device__ __forceinline__ u64 ffma2(u64 a, u64 b, u64 c) {
    u64 d; asm("fma.rn.f32x2 %0, %1, %2, %3;" : "=l"(d) : "l"(a), "l"(b), "l"(c));
    return d;
}
static __device__ __forceinline__ u64 dup2(float x) {
    u64 r; asm("mov.b64 %0, {%1, %1};" : "=l"(r) : "f"(x)); return r;
}
static __device__ __forceinline__ float2 u2f(u64 v) {
    float2 f; asm("mov.b64 {%0, %1}, %2;" : "=f"(f.x), "=f"(f.y) : "l"(v)); return f;
}
static __device__ __forceinline__ float sigm(float x)  { return 1.f / (1.f + expf(-x)); }
static __device__ __forceinline__ float siluf(float x) { return x / (1.f + expf(-x)); }
static __device__ __forceinline__ float softp(float x) { return (x > 20.f) ? x : log1pf(expf(x)); }

static __device__ __forceinline__ void grid_sync() {
    __syncthreads();
    if (threadIdx.x == 0) {
        unsigned gen = *((volatile unsigned*)&g_bar_gen);
        __threadfence();
        if (atomicAdd(&g_bar_count, 1u) == NB - 1) {
            *((volatile unsigned*)&g_bar_count) = 0;
            __threadfence();
            atomicExch(&g_bar_gen, gen + 1);
        } else {
            while (*((volatile unsigned*)&g_bar_gen) == gen) { }
        }
        __threadfence();
    }
    __syncthreads();
}

static __device__ __forceinline__ float block_sum_256(float v, float* red) {
    int lane = threadIdx.x & 31, wid = threadIdx.x >> 5;
#pragma unroll
    for (int o = 16; o; o >>= 1) v += __shfl_xor_sync(0xffffffffu, v, o);
    __syncthreads();
    if (lane == 0) red[wid] = v;
    __syncthreads();
    float s = ((red[0] + red[1]) + (red[2] + red[3]))
            + ((red[4] + red[5]) + (red[6] + red[7]));
    return s;
}

// ---------------- init A (CTA 0) ----------------
static __device__ void initA_body(
    float* sm, float* red,
    const float* __restrict__ initial_deter,
    const float* __restrict__ w_po, const float* __restrict__ g_po, const float* __restrict__ bb_po,
    const float* __restrict__ w_ps, const float* __restrict__ b_ps)
{
    const int tid = threadIdx.x;
    float* d0s = sm;
    float* h0s = sm + 512;
#pragma unroll
    for (int i = 0; i < 2; i++) {
        int j = tid + 256 * i;
        float v = tanhf(initial_deter[j]);
        d0s[j] = v; g_init[j] = v;
    }
    __syncthreads();
    float p[2] = {0.f, 0.f};
    for (int k = 0; k < 512; k++) {
        float dv = d0s[k];
#pragma unroll
        for (int i = 0; i < 2; i++) p[i] += dv * w_po[(size_t)k * 512 + tid + 256 * i];
    }
    float mean = block_sum_256(p[0] + p[1], red) * (1.f / 512.f);
    float e[2], vs = 0.f;
#pragma unroll
    for (int i = 0; i < 2; i++) { e[i] = p[i] - mean; vs += e[i] * e[i]; }
    float var = block_sum_256(vs, red) * (1.f / 512.f);
    float rstd = rsqrtf(var + 1e-3f);
#pragma unroll
    for (int i = 0; i < 2; i++) {
        int j = tid + 256 * i;
        h0s[j] = siluf(e[i] * rstd * g_po[j] + bb_po[j]);
    }
    __syncthreads();
    if (tid < STOCHv) {
        float s0 = 0.f, s1 = 0.f, s2 = 0.f, s3 = 0.f;
        for (int k = 0; k < 512; k += 4) {
            s0 += h0s[k]     * w_ps[(size_t)k * 64 + tid];
            s1 += h0s[k + 1] * w_ps[(size_t)(k + 1) * 64 + tid];
            s2 += h0s[k + 2] * w_ps[(size_t)(k + 2) * 64 + tid];
            s3 += h0s[k + 3] * w_ps[(size_t)(k + 3) * 64 + tid];
        }
        g_init[DETERv + tid] = b_ps[tid] + ((s0 + s1) + (s2 + s3));
    }
    __syncthreads();
}

// prior_in for one row (init only), x36 in smem
static __device__ void prior_in_body(
    float* x36, float* red, int b,
    const float* __restrict__ w_pi, const float* __restrict__ g_pi, const float* __restrict__ bb_pi)
{
    const int tid = threadIdx.x;
    float p[2] = {0.f, 0.f};
#pragma unroll
    for (int k = 0; k < 36; k++) {
        float xv = x36[k];
#pragma unroll
        for (int i = 0; i < 2; i++) p[i] += xv * w_pi[(size_t)k * HIDv + tid + 256 * i];
    }
    float mean = block_sum_256(p[0] + p[1], red) * (1.f / 512.f);
    float e[2], vs = 0.f;
#pragma unroll
    for (int i = 0; i < 2; i++) { e[i] = p[i] - mean; vs += e[i] * e[i]; }
    float var = block_sum_256(vs, red) * (1.f / 512.f);
    float rstd = rsqrtf(var + 1e-3f);
    float* xc = g_xcat + (size_t)b * 1024;
#pragma unroll
    for (int i = 0; i < 2; i++) {
        int j = tid + 256 * i;
        xc[j] = siluf(e[i] * rstd * g_pi[j] + bb_pi[j]);
    }
}

// ---- gates GEMM [256,1024]@[1024,1536]: 2M(128) x 16N(96) x ksplit8(K=128) ----
// M-packed f32x2, double-buffered smem (1 syncthreads/kt), direct u64 A-frags.
#define AS_S 132
#define BS_SG 100
#define GSTG 3712   // stage = A 16*132 + B 16*100
static __device__ void gates_body(float* sm, int bid, const float* __restrict__ w_gru)
{
    const int tid = threadIdx.x;
    const int row0 = (bid & 1) * 128;
    const int col0 = ((bid >> 1) & 15) * 96;
    const int kz   = bid >> 5;
    const int K0   = kz * 128;
    const int tx = tid & 15, ty = tid >> 4;

    u64 acc[4][6];
#pragma unroll
    for (int p = 0; p < 4; p++)
#pragma unroll
        for (int c = 0; c < 6; c++) acc[p][c] = 0ull;

    const int ar = tid >> 1, akg = (tid & 1) * 8;
    const float* Ap = g_xcat + (size_t)(row0 + ar) * 1024 + K0 + akg;
    const int bk0 = tid / 24,         bn0 = (tid % 24) * 4;
    const bool hasB1 = (tid < 128);
    const int bk1 = (tid + 256) / 24, bn1 = ((tid + 256) % 24) * 4;
    const float* Bp0 = w_gru + (size_t)(K0 + bk0) * GATESv + col0 + bn0;
    const float* Bp1 = w_gru + (size_t)(K0 + bk1) * GATESv + col0 + bn1;

    float4 a0 = *(const float4*)Ap;
    float4 a1 = *(const float4*)(Ap + 4);
    float4 b0 = *(const float4*)Bp0;
    float4 b1 = hasB1 ? *(const float4*)Bp1 : make_float4(0.f, 0.f, 0.f, 0.f);

    // prologue: stage 0 store, then load kt=1 regs
    {
        float* S = sm;
        float v[8] = {a0.x, a0.y, a0.z, a0.w, a1.x, a1.y, a1.z, a1.w};
#pragma unroll
        for (int j = 0; j < 8; j++) S[(akg + j) * AS_S + ar] = v[j];
        float* SB = sm + 2112;
        *(float4*)&SB[bk0 * BS_SG + bn0] = b0;
        if (hasB1) *(float4*)&SB[bk1 * BS_SG + bn1] = b1;
    }
    a0 = *(const float4*)(Ap + 16);
    a1 = *(const float4*)(Ap + 20);
    b0 = *(const float4*)(Bp0 + (size_t)16 * GATESv);
    if (hasB1) b1 = *(const float4*)(Bp1 + (size_t)16 * GATESv);
    __syncthreads();

    for (int kt = 0; kt < 8; kt++) {
        float* cur = sm + (kt & 1) * GSTG;
        if (kt + 1 < 8) {
            float* S = sm + ((kt + 1) & 1) * GSTG;
            float v[8] = {a0.x, a0.y, a0.z, a0.w, a1.x, a1.y, a1.z, a1.w};
#pragma unroll
            for (int j = 0; j < 8; j++) S[(akg + j) * AS_S + ar] = v[j];
            float* SB = S + 2112;
            *(float4*)&SB[bk0 * BS_SG + bn0] = b0;
            if (hasB1) *(float4*)&SB[bk1 * BS_SG + bn1] = b1;
        }
        if (kt + 2 < 8) {
            a0 = *(const float4*)(Ap + (size_t)(kt + 2) * 16);
            a1 = *(const float4*)(Ap + (size_t)(kt + 2) * 16 + 4);
            b0 = *(const float4*)(Bp0 + (size_t)(kt + 2) * 16 * GATESv);
            if (hasB1) b1 = *(const float4*)(Bp1 + (size_t)(kt + 2) * 16 * GATESv);
        }
#pragma unroll 4
        for (int k = 0; k < 16; k++) {
            const u64* app = (const u64*)(cur + k * AS_S + ty * 8);
            u64 ap0 = app[0], ap1 = app[1], ap2 = app[2], ap3 = app[3];
            const float* Bc = cur + 2112 + k * BS_SG + 2 * tx;
#pragma unroll
            for (int q = 0; q < 3; q++) {
                float2 bq = *(const float2*)(Bc + 32 * q);
                u64 d0 = dup2(bq.x), d1 = dup2(bq.y);
                acc[0][2 * q]     = ffma2(ap0, d0, acc[0][2 * q]);
                acc[0][2 * q + 1] = ffma2(ap0, d1, acc[0][2 * q + 1]);
                acc[1][2 * q]     = ffma2(ap1, d0, acc[1][2 * q]);
                acc[1][2 * q + 1] = ffma2(ap1, d1, acc[1][2 * q + 1]);
                acc[2][2 * q]     = ffma2(ap2, d0, acc[2][2 * q]);
                acc[2][2 * q + 1] = ffma2(ap2, d1, acc[2][2 * q + 1]);
                acc[3][2 * q]     = ffma2(ap3, d0, acc[3][2 * q]);
                acc[3][2 * q + 1] = ffma2(ap3, d1, acc[3][2 * q + 1]);
            }
        }
        __syncthreads();
    }
    float* G = g_gates[kz];
#pragma unroll
    for (int p = 0; p < 4; p++) {
        float2 c0v = u2f(acc[p][0]), c1v = u2f(acc[p][1]);
        float2 c2v = u2f(acc[p][2]), c3v = u2f(acc[p][3]);
        float2 c4v = u2f(acc[p][4]), c5v = u2f(acc[p][5]);
        size_t rA = (size_t)(row0 + ty * 8 + 2 * p) * GATESv + col0 + 2 * tx;
        size_t rB = rA + GATESv;
        *(float2*)&G[rA]      = make_float2(c0v.x, c1v.x);
        *(float2*)&G[rA + 32] = make_float2(c2v.x, c3v.x);
        *(float2*)&G[rA + 64] = make_float2(c4v.x, c5v.x);
        *(float2*)&G[rB]      = make_float2(c0v.y, c1v.y);
        *(float2*)&G[rB + 32] = make_float2(c2v.y, c3v.y);
        *(float2*)&G[rB + 64] = make_float2(c4v.y, c5v.y);
    }
}

// ---- GRU for row b (1 row/CTA) ----
static __device__ void gru_row_body(
    float* gs, float* red, int b,
    const float* __restrict__ g_g, const float* __restrict__ bb_g,
    float* __restrict__ out, int t)
{
    const int tid = threadIdx.x;
    float s = 0.f;
#pragma unroll
    for (int i = 0; i < 6; i++) {
        int c = tid + 256 * i;
        float v = 0.f;
#pragma unroll
        for (int kz = 0; kz < 8; kz++) v += g_gates[kz][(size_t)b * GATESv + c];
        gs[c] = v; s += v;
    }
    float mean = block_sum_256(s, red) * (1.f / 1536.f);
    float vs = 0.f;
#pragma unroll
    for (int i = 0; i < 6; i++) {
        float e = gs[tid + 256 * i] - mean; vs += e * e;
    }
    float var = block_sum_256(vs, red) * (1.f / 1536.f);
    float rstd = rsqrtf(var + 1e-3f);

    float* ob = out + ((size_t)b * Tv + t) * OUTCv;
    const float* xc = g_xcat + (size_t)b * 1024 + 512;
#pragma unroll
    for (int i = 0; i < 2; i++) {
        int j = tid + 256 * i;
        float gr = (gs[j] - mean) * rstd * g_g[j] + bb_g[j];
        float gc = (gs[j + 512] - mean) * rstd * g_g[j + 512] + bb_g[j + 512];
        float gu = (gs[j + 1024] - mean) * rstd * g_g[j + 1024] + bb_g[j + 1024];
        float r = sigm(gr);
        float u = sigm(gu - 1.0f);
        float cand = siluf(r * gc);
        float d = u * cand + (1.f - u) * xc[j];
        g_deter[(size_t)b * 512 + j] = d;
        ob[j] = d;
        ob[608 + j] = d;
    }
}

// ---- mm GEMMs: 2M(128) x 8N(64) x 2z x ksplit8(K=64); double-buffered ----
#define BS_SM 68
static __device__ void mm_body(
    float* sm, int bid,
    const float* __restrict__ w_po, const float* __restrict__ w_post,
    const float* __restrict__ obs, int t)
{
    const int tid = threadIdx.x;
    const int m2 = bid & 1;
    const int c0 = ((bid >> 1) & 7) * 64;
    const int z  = (bid >> 4) & 1;
    const int kz = bid >> 5;
    const int K0 = kz * 64;
    const int tx = tid & 15, ty = tid >> 4;
    const float* W = z ? w_post : w_po;

    u64 acc[4][4];
#pragma unroll
    for (int p = 0; p < 4; p++)
#pragma unroll
        for (int c = 0; c < 4; c++) acc[p][c] = 0ull;

    const int ar = tid >> 1, akg = (tid & 1) * 8;
    const float* Ap = g_deter + (size_t)(m2 * 128 + ar) * 512 + K0 + akg;
    const int bk = tid >> 4, bn = (tid & 15) * 4;
    const float* Bp = W + (size_t)(K0 + bk) * 512 + c0 + bn;

    float4 a0 = *(const float4*)Ap;
    float4 a1 = *(const float4*)(Ap + 4);
    float4 b0 = *(const float4*)Bp;

    {
        float* S = sm;
        float v[8] = {a0.x, a0.y, a0.z, a0.w, a1.x, a1.y, a1.z, a1.w};
#pragma unroll
        for (int j = 0; j < 8; j++) S[(akg + j) * AS_S + ar] = v[j];
        *(float4*)&S[2112 + bk * BS_SM + bn] = b0;
    }
    a0 = *(const float4*)(Ap + 16);
    a1 = *(const float4*)(Ap + 20);
    b0 = *(const float4*)(Bp + (size_t)16 * 512);
    __syncthreads();

    for (int kt = 0; kt < 4; kt++) {
        float* cur = sm + (kt & 1) * GSTG;
        if (kt + 1 < 4) {
            float* S = sm + ((kt + 1) & 1) * GSTG;
            float v[8] = {a0.x, a0.y, a0.z, a0.w, a1.x, a1.y, a1.z, a1.w};
#pragma unroll
            for (int j = 0; j < 8; j++) S[(akg + j) * AS_S + ar] = v[j];
            *(float4*)&S[2112 + bk * BS_SM + bn] = b0;
        }
        if (kt + 2 < 4) {
            a0 = *(const float4*)(Ap + (size_t)(kt + 2) * 16);
            a1 = *(const float4*)(Ap + (size_t)(kt + 2) * 16 + 4);
            b0 = *(const float4*)(Bp + (size_t)(kt + 2) * 16 * 512);
        }
#pragma unroll 4
        for (int k = 0; k < 16; k++) {
            const u64* app = (const u64*)(cur + k * AS_S + ty * 8);
            u64 ap0 = app[0], ap1 = app[1], ap2 = app[2], ap3 = app[3];
            const float* Bc = cur + 2112 + k * BS_SM + 2 * tx;
#pragma unroll
            for (int q = 0; q < 2; q++) {
                float2 bq = *(const float2*)(Bc + 32 * q);
                u64 d0 = dup2(bq.x), d1 = dup2(bq.y);
                acc[0][2 * q]     = ffma2(ap0, d0, acc[0][2 * q]);
                acc[0][2 * q + 1] = ffma2(ap0, d1, acc[0][2 * q + 1]);
                acc[1][2 * q]     = ffma2(ap1, d0, acc[1][2 * q]);
                acc[1][2 * q + 1] = ffma2(ap1, d1, acc[1][2 * q + 1]);
                acc[2][2 * q]     = ffma2(ap2, d0, acc[2][2 * q]);
                acc[2][2 * q + 1] = ffma2(ap2, d1, acc[2][2 * q + 1]);
                acc[3][2 * q]     = ffma2(ap3, d0, acc[3][2 * q]);
                acc[3][2 * q + 1] = ffma2(ap3, d1, acc[3][2 * q + 1]);
            }
        }
        __syncthreads();
    }

    if (z == 1 && kz == 7) {   // obs tail: K rows 512..529 of w_post
        float* obs_s = sm;          // [18][132]
        float* wb_s  = sm + 2400;   // [18][68]
#pragma unroll
        for (int q = 0; q < 9; q++) {
            int e = q * 256 + tid;
            int row = e / 18, k = e % 18;
            obs_s[k * AS_S + row] = obs[((size_t)(m2 * 128 + row) * Tv + t) * OBSv + k];
        }
#pragma unroll
        for (int q = 0; q < 5; q++) {
            int e = q * 256 + tid;
            if (e < 1152) {
                int k = e / 64, n = e % 64;
                wb_s[k * BS_SM + n] = w_post[(size_t)(512 + k) * 512 + c0 + n];
            }
        }
        __syncthreads();
#pragma unroll 2
        for (int k = 0; k < OBSv; k++) {
            const u64* app = (const u64*)(obs_s + k * AS_S + ty * 8);
            u64 ap0 = app[0], ap1 = app[1], ap2 = app[2], ap3 = app[3];
#pragma unroll
            for (int q = 0; q < 2; q++) {
                float2 bq = *(const float2*)(wb_s + k * BS_SM + 2 * tx + 32 * q);
                u64 d0 = dup2(bq.x), d1 = dup2(bq.y);
                acc[0][2 * q]     = ffma2(ap0, d0, acc[0][2 * q]);
                acc[0][2 * q + 1] = ffma2(ap0, d1, acc[0][2 * q + 1]);
                acc[1][2 * q]     = ffma2(ap1, d0, acc[1][2 * q]);
                acc[1][2 * q + 1] = ffma2(ap1, d1, acc[1][2 * q + 1]);
                acc[2][2 * q]     = ffma2(ap2, d0, acc[2][2 * q]);
                acc[2][2 * q + 1] = ffma2(ap2, d1, acc[2][2 * q + 1]);
                acc[3][2 * q]     = ffma2(ap3, d0, acc[3][2 * q]);
                acc[3][2 * q + 1] = ffma2(ap3, d1, acc[3][2 * q + 1]);
            }
        }
        __syncthreads();
    }

    float* Gm = g_mm[z][kz];
#pragma unroll
    for (int p = 0; p < 4; p++) {
        float2 c0v = u2f(acc[p][0]), c1v = u2f(acc[p][1]);
        float2 c2v = u2f(acc[p][2]), c3v = u2f(acc[p][3]);
        size_t rA = (size_t)(m2 * 128 + ty * 8 + 2 * p) * 512 + c0 + 2 * tx;
        size_t rB = rA + 512;
        *(float2*)&Gm[rA]      = make_float2(c0v.x, c1v.x);
        *(float2*)&Gm[rA + 32] = make_float2(c2v.x, c3v.x);
        *(float2*)&Gm[rB]      = make_float2(c0v.y, c1v.y);
        *(float2*)&Gm[rB + 32] = make_float2(c2v.y, c3v.y);
    }
}

// ---- T2 (merged T1): reduce+LN + stats + outputs + prior_in + xcat, 4 rows/CTA ----
static __device__ void t2_body(
    float* sm, float* red, int bid,
    const float* __restrict__ g_po, const float* __restrict__ bb_po,
    const float* __restrict__ g_pq, const float* __restrict__ bb_pq,
    const float* __restrict__ w_ps, const float* __restrict__ b_ps,
    const float* __restrict__ w_qs, const float* __restrict__ b_qs,
    const float* __restrict__ w_pi, const float* __restrict__ g_pi, const float* __restrict__ bb_pi,
    const float* __restrict__ action, const int* __restrict__ is_first,
    float* __restrict__ out, int t)
{
    const int tid = threadIdx.x;
    float* hs    = sm;          // [2][512][4]
    float* ppart = sm + 4096;   // [2][128][4]
    float* st    = sm + 5120;   // [128][4]
    float* x36s  = sm + 5632;   // [36][4]
    float* fs    = sm + 5780;   // [4]
    const int r0 = bid * 4;

    if (tid < 4 && t + 1 < Tv) fs[tid] = (float)is_first[(size_t)(r0 + tid) * Tv + t + 1];

    // merged T1: per (z,row) reduce split-K + LN + silu into hs[k][r]
#pragma unroll
    for (int z = 0; z < 2; z++) {
        const float* gg = z ? g_pq : g_po;
        const float* gb = z ? bb_pq : bb_po;
#pragma unroll
        for (int r = 0; r < 4; r++) {
            float a0 = 0.f, a1 = 0.f;
#pragma unroll
            for (int kz = 0; kz < 8; kz++) {
                const float* src = g_mm[z][kz] + (size_t)(r0 + r) * 512;
                a0 += src[tid]; a1 += src[tid + 256];
            }
            float mean = block_sum_256(a0 + a1, red) * (1.f / 512.f);
            float e0 = a0 - mean, e1 = a1 - mean;
            float var = block_sum_256(e0 * e0 + e1 * e1, red) * (1.f / 512.f);
            float rstd = rsqrtf(var + 1e-3f);
            hs[z * 2048 + tid * 4 + r]         = siluf(e0 * rstd * gg[tid] + gb[tid]);
            hs[z * 2048 + (tid + 256) * 4 + r] = siluf(e1 * rstd * gg[tid + 256] + gb[tid + 256]);
        }
    }
    __syncthreads();

    // stats: 128 outs x 2 k-halves
    {
        const int khalf = tid >> 7;
        const int j = tid & 127;
        const int zsel = j >> 6;
        const int jj = j & 63;
        const float* W = zsel ? w_qs : w_ps;
        const float* hb = hs + zsel * 2048;
        float a0 = 0.f, a1 = 0.f, a2 = 0.f, a3 = 0.f;
        const int kb = khalf * 256;
#pragma unroll 4
        for (int k = 0; k < 256; k++) {
            float w = W[(size_t)(kb + k) * 64 + jj];
            float4 h4 = *(const float4*)(hb + (kb + k) * 4);
            a0 += h4.x * w; a1 += h4.y * w; a2 += h4.z * w; a3 += h4.w * w;
        }
        float* pp = ppart + khalf * 512 + j * 4;
        pp[0] = a0; pp[1] = a1; pp[2] = a2; pp[3] = a3;
    }
    __syncthreads();
    if (tid < 128) {
        const int j = tid;
        const int zsel = j >> 6, jj = j & 63;
        float bias = zsel ? b_qs[jj] : b_ps[jj];
#pragma unroll
        for (int r = 0; r < 4; r++) {
            float s = ppart[j * 4 + r] + ppart[512 + j * 4 + r] + bias;
            st[j * 4 + r] = s;
            float* ob = out + ((size_t)(r0 + r) * Tv + t) * OUTCv;
            if (zsel == 0) {      // prior stats
                if (jj < 32) { ob[1120 + jj] = s; ob[1152 + jj] = s; }
                else          ob[1184 + jj - 32] = softp(s) + 0.1f;
            } else {              // post stats
                if (jj < 32) { ob[512 + jj] = s; ob[544 + jj] = s; }
                else          ob[576 + jj - 32] = softp(s) + 0.1f;
            }
        }
    }
    __syncthreads();

    if (t + 1 >= Tv) return;

    if (tid < 144) {
        int k = tid >> 2, r = tid & 3;
        bool f = fs[r] > 0.f;
        float v;
        if (k < 32) v = f ? g_init[DETERv + k] : st[(64 + k) * 4 + r];
        else        v = f ? 0.f : action[((size_t)(r0 + r) * Tv + t + 1) * ACTv + (k - 32)];
        x36s[k * 4 + r] = v;
    }
    __syncthreads();

    float acc[4][2];
#pragma unroll
    for (int r = 0; r < 4; r++) { acc[r][0] = 0.f; acc[r][1] = 0.f; }
#pragma unroll 4
    for (int k = 0; k < 36; k++) {
        float4 x4 = *(const float4*)(x36s + k * 4);
        float w0 = w_pi[(size_t)k * HIDv + tid];
        float w1 = w_pi[(size_t)k * HIDv + tid + 256];
        acc[0][0] += x4.x * w0; acc[0][1] += x4.x * w1;
        acc[1][0] += x4.y * w0; acc[1][1] += x4.y * w1;
        acc[2][0] += x4.z * w0; acc[2][1] += x4.z * w1;
        acc[3][0] += x4.w * w0; acc[3][1] += x4.w * w1;
    }
#pragma unroll
    for (int r = 0; r < 4; r++) {
        float mean = block_sum_256(acc[r][0] + acc[r][1], red) * (1.f / 512.f);
        float e0 = acc[r][0] - mean, e1 = acc[r][1] - mean;
        float var = block_sum_256(e0 * e0 + e1 * e1, red) * (1.f / 512.f);
        float rstd = rsqrtf(var + 1e-3f);
        float* xc = g_xcat + (size_t)(r0 + r) * 1024;
        xc[tid]       = siluf(e0 * rstd * g_pi[tid] + bb_pi[tid]);
        xc[tid + 256] = siluf(e1 * rstd * g_pi[tid + 256] + bb_pi[tid + 256]);
        bool f = fs[r] > 0.f;
        const float* dsrc = g_deter + (size_t)(r0 + r) * 512;
#pragma unroll
        for (int i = 0; i < 2; i++) {
            int j = tid + 256 * i;
            xc[512 + j] = f ? g_init[j] : dsrc[j];
        }
    }
}

// ---------------- persistent kernel ----------------
__global__ __launch_bounds__(256, 2) void k_rssm(
    const float* __restrict__ obs, const float* __restrict__ action,
    const int* __restrict__ is_first,
    const float* __restrict__ w_pi, const float* __restrict__ g_pi, const float* __restrict__ bb_pi,
    const float* __restrict__ w_gru, const float* __restrict__ g_g, const float* __restrict__ bb_g,
    const float* __restrict__ w_po, const float* __restrict__ g_po, const float* __restrict__ bb_po,
    const float* __restrict__ w_ps, const float* __restrict__ b_ps,
    const float* __restrict__ w_post, const float* __restrict__ g_pq, const float* __restrict__ bb_pq,
    const float* __restrict__ w_qs, const float* __restrict__ b_qs,
    const float* __restrict__ init_deter,
    float* __restrict__ out)
{
    __shared__ float sm[7432];   // 2 x GSTG(3712) stage buffers; t2 reuses [0..5832)
    float* red = sm + 7424;
    const int bid = blockIdx.x;
    const int tid = threadIdx.x;

    if (bid == 0)
        initA_body(sm, red, init_deter, w_po, g_po, bb_po, w_ps, b_ps);
    grid_sync();

    {   // init xcat for t=0 (1 row/CTA)
        float* x36 = sm + 5632;
        const int b = bid;
        const int f = is_first[(size_t)b * Tv];
        if (tid < 32) x36[tid] = g_init[DETERv + tid];
        else if (tid < 36) x36[tid] = (f > 0) ? 0.f : action[(size_t)b * Tv * ACTv + (tid - 32)];
        __syncthreads();
        prior_in_body(x36, red, b, w_pi, g_pi, bb_pi);
        float* xc = g_xcat + (size_t)b * 1024;
#pragma unroll
        for (int i = 0; i < 2; i++) {
            int j = tid + 256 * i;
            xc[512 + j] = g_init[j];
        }
        __syncthreads();
    }
    grid_sync();

    for (int t = 0; t < Tv; t++) {
        gates_body(sm, bid, w_gru);
        grid_sync();

        gru_row_body(sm, red, bid, g_g, bb_g, out, t);
        grid_sync();

        mm_body(sm, bid, w_po, w_post, obs, t);
        grid_sync();

        if (bid < 64)
            t2_body(sm, red, bid,
                    g_po, bb_po, g_pq, bb_pq,
                    w_ps, b_ps, w_qs, b_qs,
                    w_pi, g_pi, bb_pi, action, is_first, out, t);
        grid_sync();
    }
}

extern "C" void kernel_launch(void* const* d_in, const int* in_sizes, int n_in,
                              void* d_out, int out_size)
{
    const float* obs        = (const float*)d_in[0];
    const float* action     = (const float*)d_in[1];
    const int*   is_first   = (const int*)d_in[2];
    const float* w_prior_in = (const float*)d_in[3];
    const float* g_prior_in = (const float*)d_in[4];
    const float* bb_prior_in= (const float*)d_in[5];
    const float* w_gru      = (const float*)d_in[6];
    const float* g_gru_p    = (const float*)d_in[7];
    const float* bb_gru_p   = (const float*)d_in[8];
    const float* w_prior_out= (const float*)d_in[9];
    const float* g_prior_out= (const float*)d_in[10];
    const float* bb_prior_out=(const float*)d_in[11];
    const float* w_prior_st = (const float*)d_in[12];
    const float* b_prior_st = (const float*)d_in[13];
    const float* w_post     = (const float*)d_in[14];
    const float* g_post     = (const float*)d_in[15];
    const float* bb_post    = (const float*)d_in[16];
    const float* w_post_st  = (const float*)d_in[17];
    const float* b_post_st  = (const float*)d_in[18];
    const float* init_deter = (const float*)d_in[19];
    float* out = (float*)d_out;

    k_rssm<<<NB, 256>>>(obs, action, is_first,
                        w_prior_in, g_prior_in, bb_prior_in,
                        w_gru, g_gru_p, bb_gru_p,
                        w_prior_out, g_prior_out, bb_prior_out,
                        w_prior_st, b_prior_st,
                        w_post, g_post, bb_post,
                        w_post_st, b_post_st,
                        init_deter, out);
}

// round 14
// speedup vs baseline: 1.2181x; 1.2181x over previous
#include <cuda_runtime.h>
#include <math.h>

#define Bv 256
#define Tv 256
#define STOCHv 32
#define DETERv 512
#define HIDv 512
#define OBSv 18
#define ACTv 4
#define GATESv 1536
#define OUTCv 1216
#define NB 256

__device__ float g_xcat[Bv * 1024];        // [b][0:512]=h(t), [512:1024]=deter_in(t)
__device__ float g_gates[8][Bv * GATESv];  // gates split-K partials
__device__ float g_mm[2][8][Bv * HIDv];    // mm split-K partials
__device__ float g_deter[Bv * DETERv];
__device__ float g_init[DETERv + STOCHv];  // deter0, init_mean
__device__ unsigned g_bar_count;
__device__ unsigned g_bar_gen;

typedef unsigned long long u64;

static __device__ __forceinline__ u64 ffma2(u64 a, u64 b, u64 c) {
    u64 d; asm("fma.rn.f32x2 %0, %1, %2, %3;" : "=l"(d) : "l"(a), "l"(b), "l"(c));
    return d;
}
static __device__ __forceinline__ u64 dup2(float x) {
    u64 r; asm("mov.b64 %0, {%1, %1};" : "=l"(r) : "f"(x)); return r;
}
static __device__ __forceinline__ float2 u2f(u64 v) {
    float2 f; asm("mov.b64 {%0, %1}, %2;" : "=f"(f.x), "=f"(f.y) : "l"(v)); return f;
}
static __device__ __forceinline__ float sigm(float x)  { return 1.f / (1.f + expf(-x)); }
static __device__ __forceinline__ float siluf(float x) { return x / (1.f + expf(-x)); }
static __device__ __forceinline__ float softp(float x) { return (x > 20.f) ? x : log1pf(expf(x)); }

static __device__ __forceinline__ void grid_sync() {
    __syncthreads();
    if (threadIdx.x == 0) {
        unsigned gen = *((volatile unsigned*)&g_bar_gen);
        __threadfence();
        if (atomicAdd(&g_bar_count, 1u) == NB - 1) {
            *((volatile unsigned*)&g_bar_count) = 0;
            __threadfence();
            atomicExch(&g_bar_gen, gen + 1);
        } else {
            while (*((volatile unsigned*)&g_bar_gen) == gen) { }
        }
        __threadfence();
    }
    __syncthreads();
}

static __device__ __forceinline__ float block_sum_256(float v, float* red) {
    int lane = threadIdx.x & 31, wid = threadIdx.x >> 5;
#pragma unroll
    for (int o = 16; o; o >>= 1) v += __shfl_xor_sync(0xffffffffu, v, o);
    __syncthreads();
    if (lane == 0) red[wid] = v;
    __syncthreads();
    float s = ((red[0] + red[1]) + (red[2] + red[3]))
            + ((red[4] + red[5]) + (red[6] + red[7]));
    return s;
}

// ---------------- init A (CTA 0) ----------------
static __device__ void initA_body(
    float* sm, float* red,
    const float* __restrict__ initial_deter,
    const float* __restrict__ w_po, const float* __restrict__ g_po, const float* __restrict__ bb_po,
    const float* __restrict__ w_ps, const float* __restrict__ b_ps)
{
    const int tid = threadIdx.x;
    float* d0s = sm;
    float* h0s = sm + 512;
#pragma unroll
    for (int i = 0; i < 2; i++) {
        int j = tid + 256 * i;
        float v = tanhf(initial_deter[j]);
        d0s[j] = v; g_init[j] = v;
    }
    __syncthreads();
    float p[2] = {0.f, 0.f};
    for (int k = 0; k < 512; k++) {
        float dv = d0s[k];
#pragma unroll
        for (int i = 0; i < 2; i++) p[i] += dv * w_po[(size_t)k * 512 + tid + 256 * i];
    }
    float mean = block_sum_256(p[0] + p[1], red) * (1.f / 512.f);
    float e[2], vs = 0.f;
#pragma unroll
    for (int i = 0; i < 2; i++) { e[i] = p[i] - mean; vs += e[i] * e[i]; }
    float var = block_sum_256(vs, red) * (1.f / 512.f);
    float rstd = rsqrtf(var + 1e-3f);
#pragma unroll
    for (int i = 0; i < 2; i++) {
        int j = tid + 256 * i;
        h0s[j] = siluf(e[i] * rstd * g_po[j] + bb_po[j]);
    }
    __syncthreads();
    if (tid < STOCHv) {
        float s0 = 0.f, s1 = 0.f, s2 = 0.f, s3 = 0.f;
        for (int k = 0; k < 512; k += 4) {
            s0 += h0s[k]     * w_ps[(size_t)k * 64 + tid];
            s1 += h0s[k + 1] * w_ps[(size_t)(k + 1) * 64 + tid];
            s2 += h0s[k + 2] * w_ps[(size_t)(k + 2) * 64 + tid];
            s3 += h0s[k + 3] * w_ps[(size_t)(k + 3) * 64 + tid];
        }
        g_init[DETERv + tid] = b_ps[tid] + ((s0 + s1) + (s2 + s3));
    }
    __syncthreads();
}

// prior_in for one row (init only), x36 in smem
static __device__ void prior_in_body(
    float* x36, float* red, int b,
    const float* __restrict__ w_pi, const float* __restrict__ g_pi, const float* __restrict__ bb_pi)
{
    const int tid = threadIdx.x;
    float p[2] = {0.f, 0.f};
#pragma unroll
    for (int k = 0; k < 36; k++) {
        float xv = x36[k];
#pragma unroll
        for (int i = 0; i < 2; i++) p[i] += xv * w_pi[(size_t)k * HIDv + tid + 256 * i];
    }
    float mean = block_sum_256(p[0] + p[1], red) * (1.f / 512.f);
    float e[2], vs = 0.f;
#pragma unroll
    for (int i = 0; i < 2; i++) { e[i] = p[i] - mean; vs += e[i] * e[i]; }
    float var = block_sum_256(vs, red) * (1.f / 512.f);
    float rstd = rsqrtf(var + 1e-3f);
    float* xc = g_xcat + (size_t)b * 1024;
#pragma unroll
    for (int i = 0; i < 2; i++) {
        int j = tid + 256 * i;
        xc[j] = siluf(e[i] * rstd * g_pi[j] + bb_pi[j]);
    }
}

// ---- gates GEMM [256,1024]@[1024,1536]: 2M(128) x 16N(96) x ksplit8(K=128) ----
// M-packed f32x2 (R12-proven). Single-buffered.
#define AS_S 132
#define BS_SG 100
static __device__ void gates_body(float* sm, int bid, const float* __restrict__ w_gru)
{
    float* As = sm;           // [16][132]
    float* Bs = sm + 2112;    // [16][100]
    const int tid = threadIdx.x;
    const int row0 = (bid & 1) * 128;
    const int col0 = ((bid >> 1) & 15) * 96;
    const int kz   = bid >> 5;
    const int K0   = kz * 128;
    const int tx = tid & 15, ty = tid >> 4;

    u64 acc[4][6];
#pragma unroll
    for (int p = 0; p < 4; p++)
#pragma unroll
        for (int c = 0; c < 6; c++) acc[p][c] = 0ull;

    const int ar = tid >> 1, akg = (tid & 1) * 8;
    const float* Ap = g_xcat + (size_t)(row0 + ar) * 1024 + K0 + akg;
    const int bk0 = tid / 24,         bn0 = (tid % 24) * 4;
    const bool hasB1 = (tid < 128);
    const int bk1 = (tid + 256) / 24, bn1 = ((tid + 256) % 24) * 4;
    const float* Bp0 = w_gru + (size_t)(K0 + bk0) * GATESv + col0 + bn0;
    const float* Bp1 = w_gru + (size_t)(K0 + bk1) * GATESv + col0 + bn1;

    float4 a0 = *(const float4*)Ap;
    float4 a1 = *(const float4*)(Ap + 4);
    float4 b0 = *(const float4*)Bp0;
    float4 b1 = hasB1 ? *(const float4*)Bp1 : make_float4(0.f, 0.f, 0.f, 0.f);

    for (int kt = 0; kt < 8; kt++) {
        {
            float v[8] = {a0.x, a0.y, a0.z, a0.w, a1.x, a1.y, a1.z, a1.w};
#pragma unroll
            for (int j = 0; j < 8; j++) As[(akg + j) * AS_S + ar] = v[j];
        }
        *(float4*)&Bs[bk0 * BS_SG + bn0] = b0;
        if (hasB1) *(float4*)&Bs[bk1 * BS_SG + bn1] = b1;
        __syncthreads();
        if (kt + 1 < 8) {
            a0 = *(const float4*)(Ap + (size_t)(kt + 1) * 16);
            a1 = *(const float4*)(Ap + (size_t)(kt + 1) * 16 + 4);
            b0 = *(const float4*)(Bp0 + (size_t)(kt + 1) * 16 * GATESv);
            if (hasB1) b1 = *(const float4*)(Bp1 + (size_t)(kt + 1) * 16 * GATESv);
        }
#pragma unroll 4
        for (int k = 0; k < 16; k++) {
            const u64* app = (const u64*)(As + k * AS_S + ty * 8);
            u64 ap0 = app[0], ap1 = app[1], ap2 = app[2], ap3 = app[3];
            const float* Bc = Bs + k * BS_SG + 2 * tx;
#pragma unroll
            for (int q = 0; q < 3; q++) {
                float2 bq = *(const float2*)(Bc + 32 * q);
                u64 d0 = dup2(bq.x), d1 = dup2(bq.y);
                acc[0][2 * q]     = ffma2(ap0, d0, acc[0][2 * q]);
                acc[0][2 * q + 1] = ffma2(ap0, d1, acc[0][2 * q + 1]);
                acc[1][2 * q]     = ffma2(ap1, d0, acc[1][2 * q]);
                acc[1][2 * q + 1] = ffma2(ap1, d1, acc[1][2 * q + 1]);
                acc[2][2 * q]     = ffma2(ap2, d0, acc[2][2 * q]);
                acc[2][2 * q + 1] = ffma2(ap2, d1, acc[2][2 * q + 1]);
                acc[3][2 * q]     = ffma2(ap3, d0, acc[3][2 * q]);
                acc[3][2 * q + 1] = ffma2(ap3, d1, acc[3][2 * q + 1]);
            }
        }
        __syncthreads();
    }
    float* G = g_gates[kz];
#pragma unroll
    for (int p = 0; p < 4; p++) {
        float2 c0v = u2f(acc[p][0]), c1v = u2f(acc[p][1]);
        float2 c2v = u2f(acc[p][2]), c3v = u2f(acc[p][3]);
        float2 c4v = u2f(acc[p][4]), c5v = u2f(acc[p][5]);
        size_t rA = (size_t)(row0 + ty * 8 + 2 * p) * GATESv + col0 + 2 * tx;
        size_t rB = rA + GATESv;
        *(float2*)&G[rA]      = make_float2(c0v.x, c1v.x);
        *(float2*)&G[rA + 32] = make_float2(c2v.x, c3v.x);
        *(float2*)&G[rA + 64] = make_float2(c4v.x, c5v.x);
        *(float2*)&G[rB]      = make_float2(c0v.y, c1v.y);
        *(float2*)&G[rB + 32] = make_float2(c2v.y, c3v.y);
        *(float2*)&G[rB + 64] = make_float2(c4v.y, c5v.y);
    }
}

// ---- GRU for row b (1 row/CTA) ----
static __device__ void gru_row_body(
    float* gs, float* red, int b,
    const float* __restrict__ g_g, const float* __restrict__ bb_g,
    float* __restrict__ out, int t)
{
    const int tid = threadIdx.x;
    float s = 0.f;
#pragma unroll
    for (int i = 0; i < 6; i++) {
        int c = tid + 256 * i;
        float v = 0.f;
#pragma unroll
        for (int kz = 0; kz < 8; kz++) v += g_gates[kz][(size_t)b * GATESv + c];
        gs[c] = v; s += v;
    }
    float mean = block_sum_256(s, red) * (1.f / 1536.f);
    float vs = 0.f;
#pragma unroll
    for (int i = 0; i < 6; i++) {
        float e = gs[tid + 256 * i] - mean; vs += e * e;
    }
    float var = block_sum_256(vs, red) * (1.f / 1536.f);
    float rstd = rsqrtf(var + 1e-3f);

    float* ob = out + ((size_t)b * Tv + t) * OUTCv;
    const float* xc = g_xcat + (size_t)b * 1024 + 512;
#pragma unroll
    for (int i = 0; i < 2; i++) {
        int j = tid + 256 * i;
        float gr = (gs[j] - mean) * rstd * g_g[j] + bb_g[j];
        float gc = (gs[j + 512] - mean) * rstd * g_g[j + 512] + bb_g[j + 512];
        float gu = (gs[j + 1024] - mean) * rstd * g_g[j + 1024] + bb_g[j + 1024];
        float r = sigm(gr);
        float u = sigm(gu - 1.0f);
        float cand = siluf(r * gc);
        float d = u * cand + (1.f - u) * xc[j];
        g_deter[(size_t)b * 512 + j] = d;
        ob[j] = d;
        ob[608 + j] = d;
    }
}

// ---- mm GEMMs: 2M(128) x 8N(64) x 2z x ksplit8(K=64); TMp=4, TN=4 (R12) ----
#define BS_SM 68
static __device__ void mm_body(
    float* sm, int bid,
    const float* __restrict__ w_po, const float* __restrict__ w_post,
    const float* __restrict__ obs, int t)
{
    float* As = sm;           // [16][132]
    float* Bs = sm + 2112;    // [16][68]
    const int tid = threadIdx.x;
    const int m2 = bid & 1;
    const int c0 = ((bid >> 1) & 7) * 64;
    const int z  = (bid >> 4) & 1;
    const int kz = bid >> 5;
    const int K0 = kz * 64;
    const int tx = tid & 15, ty = tid >> 4;
    const float* W = z ? w_post : w_po;

    u64 acc[4][4];
#pragma unroll
    for (int p = 0; p < 4; p++)
#pragma unroll
        for (int c = 0; c < 4; c++) acc[p][c] = 0ull;

    const int ar = tid >> 1, akg = (tid & 1) * 8;
    const float* Ap = g_deter + (size_t)(m2 * 128 + ar) * 512 + K0 + akg;
    const int bk = tid >> 4, bn = (tid & 15) * 4;
    const float* Bp = W + (size_t)(K0 + bk) * 512 + c0 + bn;

    float4 a0 = *(const float4*)Ap;
    float4 a1 = *(const float4*)(Ap + 4);
    float4 b0 = *(const float4*)Bp;

    for (int kt = 0; kt < 4; kt++) {
        {
            float v[8] = {a0.x, a0.y, a0.z, a0.w, a1.x, a1.y, a1.z, a1.w};
#pragma unroll
            for (int j = 0; j < 8; j++) As[(akg + j) * AS_S + ar] = v[j];
        }
        *(float4*)&Bs[bk * BS_SM + bn] = b0;
        __syncthreads();
        if (kt + 1 < 4) {
            a0 = *(const float4*)(Ap + (size_t)(kt + 1) * 16);
            a1 = *(const float4*)(Ap + (size_t)(kt + 1) * 16 + 4);
            b0 = *(const float4*)(Bp + (size_t)(kt + 1) * 16 * 512);
        }
#pragma unroll 4
        for (int k = 0; k < 16; k++) {
            const u64* app = (const u64*)(As + k * AS_S + ty * 8);
            u64 ap0 = app[0], ap1 = app[1], ap2 = app[2], ap3 = app[3];
            const float* Bc = Bs + k * BS_SM + 2 * tx;
#pragma unroll
            for (int q = 0; q < 2; q++) {
                float2 bq = *(const float2*)(Bc + 32 * q);
                u64 d0 = dup2(bq.x), d1 = dup2(bq.y);
                acc[0][2 * q]     = ffma2(ap0, d0, acc[0][2 * q]);
                acc[0][2 * q + 1] = ffma2(ap0, d1, acc[0][2 * q + 1]);
                acc[1][2 * q]     = ffma2(ap1, d0, acc[1][2 * q]);
                acc[1][2 * q + 1] = ffma2(ap1, d1, acc[1][2 * q + 1]);
                acc[2][2 * q]     = ffma2(ap2, d0, acc[2][2 * q]);
                acc[2][2 * q + 1] = ffma2(ap2, d1, acc[2][2 * q + 1]);
                acc[3][2 * q]     = ffma2(ap3, d0, acc[3][2 * q]);
                acc[3][2 * q + 1] = ffma2(ap3, d1, acc[3][2 * q + 1]);
            }
        }
        __syncthreads();
    }

    if (z == 1 && kz == 7) {   // obs tail: K rows 512..529 of w_post
        float* obs_s = sm;          // [18][132]
        float* wb_s  = sm + 2400;   // [18][68]
#pragma unroll
        for (int q = 0; q < 9; q++) {
            int e = q * 256 + tid;
            int row = e / 18, k = e % 18;
            obs_s[k * AS_S + row] = obs[((size_t)(m2 * 128 + row) * Tv + t) * OBSv + k];
        }
#pragma unroll
        for (int q = 0; q < 5; q++) {
            int e = q * 256 + tid;
            if (e < 1152) {
                int k = e / 64, n = e % 64;
                wb_s[k * BS_SM + n] = w_post[(size_t)(512 + k) * 512 + c0 + n];
            }
        }
        __syncthreads();
#pragma unroll 2
        for (int k = 0; k < OBSv; k++) {
            const u64* app = (const u64*)(obs_s + k * AS_S + ty * 8);
            u64 ap0 = app[0], ap1 = app[1], ap2 = app[2], ap3 = app[3];
#pragma unroll
            for (int q = 0; q < 2; q++) {
                float2 bq = *(const float2*)(wb_s + k * BS_SM + 2 * tx + 32 * q);
                u64 d0 = dup2(bq.x), d1 = dup2(bq.y);
                acc[0][2 * q]     = ffma2(ap0, d0, acc[0][2 * q]);
                acc[0][2 * q + 1] = ffma2(ap0, d1, acc[0][2 * q + 1]);
                acc[1][2 * q]     = ffma2(ap1, d0, acc[1][2 * q]);
                acc[1][2 * q + 1] = ffma2(ap1, d1, acc[1][2 * q + 1]);
                acc[2][2 * q]     = ffma2(ap2, d0, acc[2][2 * q]);
                acc[2][2 * q + 1] = ffma2(ap2, d1, acc[2][2 * q + 1]);
                acc[3][2 * q]     = ffma2(ap3, d0, acc[3][2 * q]);
                acc[3][2 * q + 1] = ffma2(ap3, d1, acc[3][2 * q + 1]);
            }
        }
        __syncthreads();
    }

    float* Gm = g_mm[z][kz];
#pragma unroll
    for (int p = 0; p < 4; p++) {
        float2 c0v = u2f(acc[p][0]), c1v = u2f(acc[p][1]);
        float2 c2v = u2f(acc[p][2]), c3v = u2f(acc[p][3]);
        size_t rA = (size_t)(m2 * 128 + ty * 8 + 2 * p) * 512 + c0 + 2 * tx;
        size_t rB = rA + 512;
        *(float2*)&Gm[rA]      = make_float2(c0v.x, c1v.x);
        *(float2*)&Gm[rA + 32] = make_float2(c2v.x, c3v.x);
        *(float2*)&Gm[rB]      = make_float2(c0v.y, c1v.y);
        *(float2*)&Gm[rB + 32] = make_float2(c2v.y, c3v.y);
    }
}

// ---- tail for row b (1 row/CTA, 256 thr): reduce+LN+stats+outputs+staging ----
// (R10-proven structure)
static __device__ void tail_row_body(
    float* sm, float* red, int b,
    const float* __restrict__ g_po, const float* __restrict__ bb_po,
    const float* __restrict__ g_pq, const float* __restrict__ bb_pq,
    const float* __restrict__ w_ps, const float* __restrict__ b_ps,
    const float* __restrict__ w_qs, const float* __restrict__ b_qs,
    const float* __restrict__ w_pi, const float* __restrict__ g_pi, const float* __restrict__ bb_pi,
    const float* __restrict__ action, const int* __restrict__ is_first,
    float* __restrict__ out, int t)
{
    const int tid = threadIdx.x;
    float* h2  = sm;           // 512
    float* h3  = sm + 512;     // 512
    float* ps  = sm + 1024;    // 64
    float* qs  = sm + 1088;    // 64
    float* pp  = sm + 1152;    // 256 (stats split-k partials)
    float* x36 = sm + 1408;    // 40

#pragma unroll
    for (int z = 0; z < 2; z++) {
        float a[2] = {0.f, 0.f};
#pragma unroll
        for (int kzi = 0; kzi < 8; kzi++) {
            const float* src = g_mm[z][kzi] + (size_t)b * 512;
            a[0] += src[tid]; a[1] += src[tid + 256];
        }
        float mean = block_sum_256(a[0] + a[1], red) * (1.f / 512.f);
        float e[2], vs = 0.f;
#pragma unroll
        for (int i = 0; i < 2; i++) { e[i] = a[i] - mean; vs += e[i] * e[i]; }
        float var = block_sum_256(vs, red) * (1.f / 512.f);
        float rstd = rsqrtf(var + 1e-3f);
        const float* gg = z ? g_pq : g_po;
        const float* gb = z ? bb_pq : bb_po;
        float* hv = z ? h3 : h2;
#pragma unroll
        for (int i = 0; i < 2; i++) {
            int j = tid + 256 * i;
            hv[j] = siluf(e[i] * rstd * gg[j] + gb[j]);
        }
        __syncthreads();
    }

    // stats GEMVs: 128 outputs, split-K across thread halves
    {
        const int half = tid >> 7;        // 0: k<256, 1: k>=256
        const int tl   = tid & 127;
        const int j    = tl & 63;
        const float* hv = (tl < 64) ? h2 : h3;
        const float* W  = (tl < 64) ? w_ps : w_qs;
        const int kbase = half * 256;
        float s0 = 0.f, s1 = 0.f, s2 = 0.f, s3 = 0.f;
        for (int k = 0; k < 256; k += 4) {
            int kk = kbase + k;
            s0 += hv[kk]     * W[(size_t)kk * 64 + j];
            s1 += hv[kk + 1] * W[(size_t)(kk + 1) * 64 + j];
            s2 += hv[kk + 2] * W[(size_t)(kk + 2) * 64 + j];
            s3 += hv[kk + 3] * W[(size_t)(kk + 3) * 64 + j];
        }
        pp[tid] = (s0 + s1) + (s2 + s3);
    }
    __syncthreads();
    if (tid < 128) {
        const int j = tid & 63;
        float s = (pp[tid] + pp[tid + 128]) + ((tid < 64) ? b_ps[j] : b_qs[j]);
        if (tid < 64) ps[j] = s; else qs[j] = s;
    }
    __syncthreads();

    float* ob = out + ((size_t)b * Tv + t) * OUTCv;
    if (tid < 32) {
        float qm = qs[tid], pm = ps[tid];
        ob[512 + tid] = qm; ob[544 + tid] = qm;
        ob[1120 + tid] = pm; ob[1152 + tid] = pm;
    } else if (tid < 64) {
        int j = tid - 32;
        ob[576 + j]  = softp(qs[tid]) + 0.1f;
        ob[1184 + j] = softp(ps[tid]) + 0.1f;
    }

    if (t + 1 < Tv) {
        const int f = is_first[(size_t)b * Tv + t + 1];
        if (tid < 32) x36[tid] = (f > 0) ? g_init[DETERv + tid] : qs[tid];
        else if (tid < 36) x36[tid] = (f > 0) ? 0.f : action[((size_t)b * Tv + t + 1) * ACTv + (tid - 32)];
        __syncthreads();
        prior_in_body(x36, red, b, w_pi, g_pi, bb_pi);
        float* xc = g_xcat + (size_t)b * 1024;
        const float* dsrc = g_deter + (size_t)b * 512;
#pragma unroll
        for (int i = 0; i < 2; i++) {
            int j = tid + 256 * i;
            xc[512 + j] = (f > 0) ? g_init[j] : dsrc[j];
        }
    }
    __syncthreads();
}

// ---------------- persistent kernel ----------------
__global__ __launch_bounds__(256, 2) void k_rssm(
    const float* __restrict__ obs, const float* __restrict__ action,
    const int* __restrict__ is_first,
    const float* __restrict__ w_pi, const float* __restrict__ g_pi, const float* __restrict__ bb_pi,
    const float* __restrict__ w_gru, const float* __restrict__ g_g, const float* __restrict__ bb_g,
    const float* __restrict__ w_po, const float* __restrict__ g_po, const float* __restrict__ bb_po,
    const float* __restrict__ w_ps, const float* __restrict__ b_ps,
    const float* __restrict__ w_post, const float* __restrict__ g_pq, const float* __restrict__ bb_pq,
    const float* __restrict__ w_qs, const float* __restrict__ b_qs,
    const float* __restrict__ init_deter,
    float* __restrict__ out)
{
    __shared__ float sm[6008];
    float* red = sm + 6000;
    const int bid = blockIdx.x;
    const int tid = threadIdx.x;

    if (bid == 0)
        initA_body(sm, red, init_deter, w_po, g_po, bb_po, w_ps, b_ps);
    grid_sync();

    {   // init xcat for t=0 (1 row/CTA)
        float* x36 = sm + 1408;
        const int b = bid;
        const int f = is_first[(size_t)b * Tv];
        if (tid < 32) x36[tid] = g_init[DETERv + tid];
        else if (tid < 36) x36[tid] = (f > 0) ? 0.f : action[(size_t)b * Tv * ACTv + (tid - 32)];
        __syncthreads();
        prior_in_body(x36, red, b, w_pi, g_pi, bb_pi);
        float* xc = g_xcat + (size_t)b * 1024;
#pragma unroll
        for (int i = 0; i < 2; i++) {
            int j = tid + 256 * i;
            xc[512 + j] = g_init[j];
        }
        __syncthreads();
    }
    grid_sync();

    for (int t = 0; t < Tv; t++) {
        gates_body(sm, bid, w_gru);
        grid_sync();

        gru_row_body(sm, red, bid, g_g, bb_g, out, t);
        grid_sync();

        mm_body(sm, bid, w_po, w_post, obs, t);
        grid_sync();

        tail_row_body(sm, red, bid,
                      g_po, bb_po, g_pq, bb_pq,
                      w_ps, b_ps, w_qs, b_qs,
                      w_pi, g_pi, bb_pi,
                      action, is_first, out, t);
        grid_sync();
    }
}

extern "C" void kernel_launch(void* const* d_in, const int* in_sizes, int n_in,
                              void* d_out, int out_size)
{
    const float* obs        = (const float*)d_in[0];
    const float* action     = (const float*)d_in[1];
    const int*   is_first   = (const int*)d_in[2];
    const float* w_prior_in = (const float*)d_in[3];
    const float* g_prior_in = (const float*)d_in[4];
    const float* bb_prior_in= (const float*)d_in[5];
    const float* w_gru      = (const float*)d_in[6];
    const float* g_gru_p    = (const float*)d_in[7];
    const float* bb_gru_p   = (const float*)d_in[8];
    const float* w_prior_out= (const float*)d_in[9];
    const float* g_prior_out= (const float*)d_in[10];
    const float* bb_prior_out=(const float*)d_in[11];
    const float* w_prior_st = (const float*)d_in[12];
    const float* b_prior_st = (const float*)d_in[13];
    const float* w_post     = (const float*)d_in[14];
    const float* g_post     = (const float*)d_in[15];
    const float* bb_post    = (const float*)d_in[16];
    const float* w_post_st  = (const float*)d_in[17];
    const float* b_post_st  = (const float*)d_in[18];
    const float* init_deter = (const float*)d_in[19];
    float* out = (float*)d_out;

    k_rssm<<<NB, 256>>>(obs, action, is_first,
                        w_prior_in, g_prior_in, bb_prior_in,
                        w_gru, g_gru_p, bb_gru_p,
                        w_prior_out, g_prior_out, bb_prior_out,
                        w_prior_st, b_prior_st,
                        w_post, g_post, bb_post,
                        w_post_st, b_post_st,
                        init_deter, out);
}

// round 15
// speedup vs baseline: 1.2521x; 1.0279x over previous
#include <cuda_runtime.h>
#include <math.h>

#define Bv 256
#define Tv 256
#define STOCHv 32
#define DETERv 512
#define HIDv 512
#define OBSv 18
#define ACTv 4
#define GATESv 1536
#define OUTCv 1216
#define NB 256

__device__ float g_xcat[Bv * 1024];        // [b][0:512]=h(t), [512:1024]=deter_in(t)
__device__ float g_gates[8][Bv * GATESv];  // gates split-K partials
__device__ float g_mm[2][8][Bv * HIDv];    // mm split-K partials
__device__ float g_deter[Bv * DETERv];
__device__ float g_init[DETERv + STOCHv];  // deter0, init_mean
__device__ __align__(128) unsigned g_bar_count;  // own 128B line (no false sharing
__device__ __align__(128) unsigned g_bar_gen;    //  with the spin target)

typedef unsigned long long u64;

static __device__ __forceinline__ u64 ffma2(u64 a, u64 b, u64 c) {
    u64 d; asm("fma.rn.f32x2 %0, %1, %2, %3;" : "=l"(d) : "l"(a), "l"(b), "l"(c));
    return d;
}
static __device__ __forceinline__ u64 dup2(float x) {
    u64 r; asm("mov.b64 %0, {%1, %1};" : "=l"(r) : "f"(x)); return r;
}
static __device__ __forceinline__ float2 u2f(u64 v) {
    float2 f; asm("mov.b64 {%0, %1}, %2;" : "=f"(f.x), "=f"(f.y) : "l"(v)); return f;
}
static __device__ __forceinline__ float sigm(float x)  { return 1.f / (1.f + expf(-x)); }
static __device__ __forceinline__ float siluf(float x) { return x / (1.f + expf(-x)); }
static __device__ __forceinline__ float softp(float x) { return (x > 20.f) ? x : log1pf(expf(x)); }

static __device__ __forceinline__ void grid_sync() {
    __syncthreads();
    if (threadIdx.x == 0) {
        unsigned gen = *((volatile unsigned*)&g_bar_gen);
        __threadfence();
        if (atomicAdd(&g_bar_count, 1u) == NB - 1) {
            *((volatile unsigned*)&g_bar_count) = 0;
            __threadfence();
            atomicExch(&g_bar_gen, gen + 1);
        } else {
            while (*((volatile unsigned*)&g_bar_gen) == gen) { }
        }
        __threadfence();
    }
    __syncthreads();
}

static __device__ __forceinline__ float block_sum_256(float v, float* red) {
    int lane = threadIdx.x & 31, wid = threadIdx.x >> 5;
#pragma unroll
    for (int o = 16; o; o >>= 1) v += __shfl_xor_sync(0xffffffffu, v, o);
    __syncthreads();
    if (lane == 0) red[wid] = v;
    __syncthreads();
    float s = ((red[0] + red[1]) + (red[2] + red[3]))
            + ((red[4] + red[5]) + (red[6] + red[7]));
    return s;
}

// ---------------- init A (CTA 0) ----------------
static __device__ void initA_body(
    float* sm, float* red,
    const float* __restrict__ initial_deter,
    const float* __restrict__ w_po, const float* __restrict__ g_po, const float* __restrict__ bb_po,
    const float* __restrict__ w_ps, const float* __restrict__ b_ps)
{
    const int tid = threadIdx.x;
    float* d0s = sm;
    float* h0s = sm + 512;
#pragma unroll
    for (int i = 0; i < 2; i++) {
        int j = tid + 256 * i;
        float v = tanhf(initial_deter[j]);
        d0s[j] = v; g_init[j] = v;
    }
    __syncthreads();
    float p[2] = {0.f, 0.f};
    for (int k = 0; k < 512; k++) {
        float dv = d0s[k];
#pragma unroll
        for (int i = 0; i < 2; i++) p[i] += dv * w_po[(size_t)k * 512 + tid + 256 * i];
    }
    float mean = block_sum_256(p[0] + p[1], red) * (1.f / 512.f);
    float e[2], vs = 0.f;
#pragma unroll
    for (int i = 0; i < 2; i++) { e[i] = p[i] - mean; vs += e[i] * e[i]; }
    float var = block_sum_256(vs, red) * (1.f / 512.f);
    float rstd = rsqrtf(var + 1e-3f);
#pragma unroll
    for (int i = 0; i < 2; i++) {
        int j = tid + 256 * i;
        h0s[j] = siluf(e[i] * rstd * g_po[j] + bb_po[j]);
    }
    __syncthreads();
    if (tid < STOCHv) {
        float s0 = 0.f, s1 = 0.f, s2 = 0.f, s3 = 0.f;
        for (int k = 0; k < 512; k += 4) {
            s0 += h0s[k]     * w_ps[(size_t)k * 64 + tid];
            s1 += h0s[k + 1] * w_ps[(size_t)(k + 1) * 64 + tid];
            s2 += h0s[k + 2] * w_ps[(size_t)(k + 2) * 64 + tid];
            s3 += h0s[k + 3] * w_ps[(size_t)(k + 3) * 64 + tid];
        }
        g_init[DETERv + tid] = b_ps[tid] + ((s0 + s1) + (s2 + s3));
    }
    __syncthreads();
}

// prior_in for one row, x36 in smem
static __device__ void prior_in_body(
    float* x36, float* red, int b,
    const float* __restrict__ w_pi, const float* __restrict__ g_pi, const float* __restrict__ bb_pi)
{
    const int tid = threadIdx.x;
    float p[2] = {0.f, 0.f};
#pragma unroll
    for (int k = 0; k < 36; k++) {
        float xv = x36[k];
#pragma unroll
        for (int i = 0; i < 2; i++) p[i] += xv * w_pi[(size_t)k * HIDv + tid + 256 * i];
    }
    float mean = block_sum_256(p[0] + p[1], red) * (1.f / 512.f);
    float e[2], vs = 0.f;
#pragma unroll
    for (int i = 0; i < 2; i++) { e[i] = p[i] - mean; vs += e[i] * e[i]; }
    float var = block_sum_256(vs, red) * (1.f / 512.f);
    float rstd = rsqrtf(var + 1e-3f);
    float* xc = g_xcat + (size_t)b * 1024;
#pragma unroll
    for (int i = 0; i < 2; i++) {
        int j = tid + 256 * i;
        xc[j] = siluf(e[i] * rstd * g_pi[j] + bb_pi[j]);
    }
}

// ---- gates GEMM [256,1024]@[1024,1536]: 2M(128) x 16N(96) x ksplit8(K=128) ----
// (R12/R14-proven, unchanged)
#define AS_S 132
#define BS_SG 100
static __device__ void gates_body(float* sm, int bid, const float* __restrict__ w_gru)
{
    float* As = sm;           // [16][132]
    float* Bs = sm + 2112;    // [16][100]
    const int tid = threadIdx.x;
    const int row0 = (bid & 1) * 128;
    const int col0 = ((bid >> 1) & 15) * 96;
    const int kz   = bid >> 5;
    const int K0   = kz * 128;
    const int tx = tid & 15, ty = tid >> 4;

    u64 acc[4][6];
#pragma unroll
    for (int p = 0; p < 4; p++)
#pragma unroll
        for (int c = 0; c < 6; c++) acc[p][c] = 0ull;

    const int ar = tid >> 1, akg = (tid & 1) * 8;
    const float* Ap = g_xcat + (size_t)(row0 + ar) * 1024 + K0 + akg;
    const int bk0 = tid / 24,         bn0 = (tid % 24) * 4;
    const bool hasB1 = (tid < 128);
    const int bk1 = (tid + 256) / 24, bn1 = ((tid + 256) % 24) * 4;
    const float* Bp0 = w_gru + (size_t)(K0 + bk0) * GATESv + col0 + bn0;
    const float* Bp1 = w_gru + (size_t)(K0 + bk1) * GATESv + col0 + bn1;

    float4 a0 = *(const float4*)Ap;
    float4 a1 = *(const float4*)(Ap + 4);
    float4 b0 = *(const float4*)Bp0;
    float4 b1 = hasB1 ? *(const float4*)Bp1 : make_float4(0.f, 0.f, 0.f, 0.f);

    for (int kt = 0; kt < 8; kt++) {
        {
            float v[8] = {a0.x, a0.y, a0.z, a0.w, a1.x, a1.y, a1.z, a1.w};
#pragma unroll
            for (int j = 0; j < 8; j++) As[(akg + j) * AS_S + ar] = v[j];
        }
        *(float4*)&Bs[bk0 * BS_SG + bn0] = b0;
        if (hasB1) *(float4*)&Bs[bk1 * BS_SG + bn1] = b1;
        __syncthreads();
        if (kt + 1 < 8) {
            a0 = *(const float4*)(Ap + (size_t)(kt + 1) * 16);
            a1 = *(const float4*)(Ap + (size_t)(kt + 1) * 16 + 4);
            b0 = *(const float4*)(Bp0 + (size_t)(kt + 1) * 16 * GATESv);
            if (hasB1) b1 = *(const float4*)(Bp1 + (size_t)(kt + 1) * 16 * GATESv);
        }
#pragma unroll 4
        for (int k = 0; k < 16; k++) {
            const u64* app = (const u64*)(As + k * AS_S + ty * 8);
            u64 ap0 = app[0], ap1 = app[1], ap2 = app[2], ap3 = app[3];
            const float* Bc = Bs + k * BS_SG + 2 * tx;
#pragma unroll
            for (int q = 0; q < 3; q++) {
                float2 bq = *(const float2*)(Bc + 32 * q);
                u64 d0 = dup2(bq.x), d1 = dup2(bq.y);
                acc[0][2 * q]     = ffma2(ap0, d0, acc[0][2 * q]);
                acc[0][2 * q + 1] = ffma2(ap0, d1, acc[0][2 * q + 1]);
                acc[1][2 * q]     = ffma2(ap1, d0, acc[1][2 * q]);
                acc[1][2 * q + 1] = ffma2(ap1, d1, acc[1][2 * q + 1]);
                acc[2][2 * q]     = ffma2(ap2, d0, acc[2][2 * q]);
                acc[2][2 * q + 1] = ffma2(ap2, d1, acc[2][2 * q + 1]);
                acc[3][2 * q]     = ffma2(ap3, d0, acc[3][2 * q]);
                acc[3][2 * q + 1] = ffma2(ap3, d1, acc[3][2 * q + 1]);
            }
        }
        __syncthreads();
    }
    float* G = g_gates[kz];
#pragma unroll
    for (int p = 0; p < 4; p++) {
        float2 c0v = u2f(acc[p][0]), c1v = u2f(acc[p][1]);
        float2 c2v = u2f(acc[p][2]), c3v = u2f(acc[p][3]);
        float2 c4v = u2f(acc[p][4]), c5v = u2f(acc[p][5]);
        size_t rA = (size_t)(row0 + ty * 8 + 2 * p) * GATESv + col0 + 2 * tx;
        size_t rB = rA + GATESv;
        *(float2*)&G[rA]      = make_float2(c0v.x, c1v.x);
        *(float2*)&G[rA + 32] = make_float2(c2v.x, c3v.x);
        *(float2*)&G[rA + 64] = make_float2(c4v.x, c5v.x);
        *(float2*)&G[rB]      = make_float2(c0v.y, c1v.y);
        *(float2*)&G[rB + 32] = make_float2(c2v.y, c3v.y);
        *(float2*)&G[rB + 64] = make_float2(c4v.y, c5v.y);
    }
}

// ---- GRU for row b (1 row/CTA): smem-free, float2 loads ----
// thread owns cols {2tid, 2tid+1} of each 512-block -> r/c/u all in registers
static __device__ void gru_row_body(
    float* red, int b,
    const float* __restrict__ g_g, const float* __restrict__ bb_g,
    float* __restrict__ out, int t)
{
    const int tid = threadIdx.x;
    const int j2 = 2 * tid;
    float2 vv[3];
    float s = 0.f;
#pragma unroll
    for (int i = 0; i < 3; i++) {
        float ax = 0.f, ay = 0.f;
#pragma unroll
        for (int kz = 0; kz < 8; kz++) {
            float2 v = ((const float2*)(g_gates[kz] + (size_t)b * GATESv))[tid + 256 * i];
            ax += v.x; ay += v.y;
        }
        vv[i] = make_float2(ax, ay);
        s += ax + ay;
    }
    float mean = block_sum_256(s, red) * (1.f / 1536.f);
    float vs = 0.f;
#pragma unroll
    for (int i = 0; i < 3; i++) {
        float e0 = vv[i].x - mean, e1 = vv[i].y - mean;
        vs += e0 * e0 + e1 * e1;
    }
    float var = block_sum_256(vs, red) * (1.f / 1536.f);
    float rstd = rsqrtf(var + 1e-3f);

    float2 ggr = *(const float2*)&g_g[j2];
    float2 ggc = *(const float2*)&g_g[j2 + 512];
    float2 ggu = *(const float2*)&g_g[j2 + 1024];
    float2 gbr = *(const float2*)&bb_g[j2];
    float2 gbc = *(const float2*)&bb_g[j2 + 512];
    float2 gbu = *(const float2*)&bb_g[j2 + 1024];
    float2 xv  = *(const float2*)(g_xcat + (size_t)b * 1024 + 512 + j2);

    float r0 = sigm((vv[0].x - mean) * rstd * ggr.x + gbr.x);
    float r1 = sigm((vv[0].y - mean) * rstd * ggr.y + gbr.y);
    float c0 = (vv[1].x - mean) * rstd * ggc.x + gbc.x;
    float c1 = (vv[1].y - mean) * rstd * ggc.y + gbc.y;
    float u0 = sigm((vv[2].x - mean) * rstd * ggu.x + gbu.x - 1.0f);
    float u1 = sigm((vv[2].y - mean) * rstd * ggu.y + gbu.y - 1.0f);
    float d0 = u0 * siluf(r0 * c0) + (1.f - u0) * xv.x;
    float d1 = u1 * siluf(r1 * c1) + (1.f - u1) * xv.y;

    float2 dd = make_float2(d0, d1);
    *(float2*)(g_deter + (size_t)b * 512 + j2) = dd;
    float* ob = out + ((size_t)b * Tv + t) * OUTCv;
    *(float2*)&ob[j2] = dd;
    *(float2*)&ob[608 + j2] = dd;
}

// ---- mm GEMMs: 2M(128) x 8N(64) x 2z x ksplit8(K=64) (R12/R14, unchanged) ----
#define BS_SM 68
static __device__ void mm_body(
    float* sm, int bid,
    const float* __restrict__ w_po, const float* __restrict__ w_post,
    const float* __restrict__ obs, int t)
{
    float* As = sm;           // [16][132]
    float* Bs = sm + 2112;    // [16][68]
    const int tid = threadIdx.x;
    const int m2 = bid & 1;
    const int c0 = ((bid >> 1) & 7) * 64;
    const int z  = (bid >> 4) & 1;
    const int kz = bid >> 5;
    const int K0 = kz * 64;
    const int tx = tid & 15, ty = tid >> 4;
    const float* W = z ? w_post : w_po;

    u64 acc[4][4];
#pragma unroll
    for (int p = 0; p < 4; p++)
#pragma unroll
        for (int c = 0; c < 4; c++) acc[p][c] = 0ull;

    const int ar = tid >> 1, akg = (tid & 1) * 8;
    const float* Ap = g_deter + (size_t)(m2 * 128 + ar) * 512 + K0 + akg;
    const int bk = tid >> 4, bn = (tid & 15) * 4;
    const float* Bp = W + (size_t)(K0 + bk) * 512 + c0 + bn;

    float4 a0 = *(const float4*)Ap;
    float4 a1 = *(const float4*)(Ap + 4);
    float4 b0 = *(const float4*)Bp;

    for (int kt = 0; kt < 4; kt++) {
        {
            float v[8] = {a0.x, a0.y, a0.z, a0.w, a1.x, a1.y, a1.z, a1.w};
#pragma unroll
            for (int j = 0; j < 8; j++) As[(akg + j) * AS_S + ar] = v[j];
        }
        *(float4*)&Bs[bk * BS_SM + bn] = b0;
        __syncthreads();
        if (kt + 1 < 4) {
            a0 = *(const float4*)(Ap + (size_t)(kt + 1) * 16);
            a1 = *(const float4*)(Ap + (size_t)(kt + 1) * 16 + 4);
            b0 = *(const float4*)(Bp + (size_t)(kt + 1) * 16 * 512);
        }
#pragma unroll 4
        for (int k = 0; k < 16; k++) {
            const u64* app = (const u64*)(As + k * AS_S + ty * 8);
            u64 ap0 = app[0], ap1 = app[1], ap2 = app[2], ap3 = app[3];
            const float* Bc = Bs + k * BS_SM + 2 * tx;
#pragma unroll
            for (int q = 0; q < 2; q++) {
                float2 bq = *(const float2*)(Bc + 32 * q);
                u64 d0 = dup2(bq.x), d1 = dup2(bq.y);
                acc[0][2 * q]     = ffma2(ap0, d0, acc[0][2 * q]);
                acc[0][2 * q + 1] = ffma2(ap0, d1, acc[0][2 * q + 1]);
                acc[1][2 * q]     = ffma2(ap1, d0, acc[1][2 * q]);
                acc[1][2 * q + 1] = ffma2(ap1, d1, acc[1][2 * q + 1]);
                acc[2][2 * q]     = ffma2(ap2, d0, acc[2][2 * q]);
                acc[2][2 * q + 1] = ffma2(ap2, d1, acc[2][2 * q + 1]);
                acc[3][2 * q]     = ffma2(ap3, d0, acc[3][2 * q]);
                acc[3][2 * q + 1] = ffma2(ap3, d1, acc[3][2 * q + 1]);
            }
        }
        __syncthreads();
    }

    if (z == 1 && kz == 7) {   // obs tail: K rows 512..529 of w_post
        float* obs_s = sm;          // [18][132]
        float* wb_s  = sm + 2400;   // [18][68]
#pragma unroll
        for (int q = 0; q < 9; q++) {
            int e = q * 256 + tid;
            int row = e / 18, k = e % 18;
            obs_s[k * AS_S + row] = obs[((size_t)(m2 * 128 + row) * Tv + t) * OBSv + k];
        }
#pragma unroll
        for (int q = 0; q < 5; q++) {
            int e = q * 256 + tid;
            if (e < 1152) {
                int k = e / 64, n = e % 64;
                wb_s[k * BS_SM + n] = w_post[(size_t)(512 + k) * 512 + c0 + n];
            }
        }
        __syncthreads();
#pragma unroll 2
        for (int k = 0; k < OBSv; k++) {
            const u64* app = (const u64*)(obs_s + k * AS_S + ty * 8);
            u64 ap0 = app[0], ap1 = app[1], ap2 = app[2], ap3 = app[3];
#pragma unroll
            for (int q = 0; q < 2; q++) {
                float2 bq = *(const float2*)(wb_s + k * BS_SM + 2 * tx + 32 * q);
                u64 d0 = dup2(bq.x), d1 = dup2(bq.y);
                acc[0][2 * q]     = ffma2(ap0, d0, acc[0][2 * q]);
                acc[0][2 * q + 1] = ffma2(ap0, d1, acc[0][2 * q + 1]);
                acc[1][2 * q]     = ffma2(ap1, d0, acc[1][2 * q]);
                acc[1][2 * q + 1] = ffma2(ap1, d1, acc[1][2 * q + 1]);
                acc[2][2 * q]     = ffma2(ap2, d0, acc[2][2 * q]);
                acc[2][2 * q + 1] = ffma2(ap2, d1, acc[2][2 * q + 1]);
                acc[3][2 * q]     = ffma2(ap3, d0, acc[3][2 * q]);
                acc[3][2 * q + 1] = ffma2(ap3, d1, acc[3][2 * q + 1]);
            }
        }
        __syncthreads();
    }

    float* Gm = g_mm[z][kz];
#pragma unroll
    for (int p = 0; p < 4; p++) {
        float2 c0v = u2f(acc[p][0]), c1v = u2f(acc[p][1]);
        float2 c2v = u2f(acc[p][2]), c3v = u2f(acc[p][3]);
        size_t rA = (size_t)(m2 * 128 + ty * 8 + 2 * p) * 512 + c0 + 2 * tx;
        size_t rB = rA + 512;
        *(float2*)&Gm[rA]      = make_float2(c0v.x, c1v.x);
        *(float2*)&Gm[rA + 32] = make_float2(c2v.x, c3v.x);
        *(float2*)&Gm[rB]      = make_float2(c0v.y, c1v.y);
        *(float2*)&Gm[rB + 32] = make_float2(c2v.y, c3v.y);
    }
}

// ---- tail for row b (1 row/CTA): float2 reduce, 8-acc stats GEMV ----
static __device__ void tail_row_body(
    float* sm, float* red, int b,
    const float* __restrict__ g_po, const float* __restrict__ bb_po,
    const float* __restrict__ g_pq, const float* __restrict__ bb_pq,
    const float* __restrict__ w_ps, const float* __restrict__ b_ps,
    const float* __restrict__ w_qs, const float* __restrict__ b_qs,
    const float* __restrict__ w_pi, const float* __restrict__ g_pi, const float* __restrict__ bb_pi,
    const float* __restrict__ action, const int* __restrict__ is_first,
    float* __restrict__ out, int t)
{
    const int tid = threadIdx.x;
    const int j2 = 2 * tid;
    float* h2  = sm;           // 512
    float* h3  = sm + 512;     // 512
    float* ps  = sm + 1024;    // 64
    float* qs  = sm + 1088;    // 64
    float* pp  = sm + 1152;    // 256
    float* x36 = sm + 1408;    // 40

#pragma unroll
    for (int z = 0; z < 2; z++) {
        float ax = 0.f, ay = 0.f;
#pragma unroll
        for (int kzi = 0; kzi < 8; kzi++) {
            float2 v = ((const float2*)(g_mm[z][kzi] + (size_t)b * 512))[tid];
            ax += v.x; ay += v.y;
        }
        float mean = block_sum_256(ax + ay, red) * (1.f / 512.f);
        float e0 = ax - mean, e1 = ay - mean;
        float var = block_sum_256(e0 * e0 + e1 * e1, red) * (1.f / 512.f);
        float rstd = rsqrtf(var + 1e-3f);
        const float* gg = z ? g_pq : g_po;
        const float* gb = z ? bb_pq : bb_po;
        float2 gg2 = *(const float2*)&gg[j2];
        float2 gb2 = *(const float2*)&gb[j2];
        float* hv = z ? h3 : h2;
        hv[j2]     = siluf(e0 * rstd * gg2.x + gb2.x);
        hv[j2 + 1] = siluf(e1 * rstd * gg2.y + gb2.y);
    }
    __syncthreads();

    // stats GEMVs: 128 outputs, split-K across thread halves, 8-way MLP
    {
        const int half = tid >> 7;
        const int tl   = tid & 127;
        const int j    = tl & 63;
        const float* hv = (tl < 64) ? h2 : h3;
        const float* W  = (tl < 64) ? w_ps : w_qs;
        const int kbase = half * 256;
        float s[8];
#pragma unroll
        for (int u = 0; u < 8; u++) s[u] = 0.f;
#pragma unroll 2
        for (int k = 0; k < 256; k += 8) {
#pragma unroll
            for (int u = 0; u < 8; u++) {
                int kk = kbase + k + u;
                s[u] += hv[kk] * W[(size_t)kk * 64 + j];
            }
        }
        pp[tid] = ((s[0] + s[1]) + (s[2] + s[3])) + ((s[4] + s[5]) + (s[6] + s[7]));
    }
    __syncthreads();
    if (tid < 128) {
        const int j = tid & 63;
        float s = (pp[tid] + pp[tid + 128]) + ((tid < 64) ? b_ps[j] : b_qs[j]);
        if (tid < 64) ps[j] = s; else qs[j] = s;
    }
    __syncthreads();

    float* ob = out + ((size_t)b * Tv + t) * OUTCv;
    if (tid < 32) {
        float qm = qs[tid], pm = ps[tid];
        ob[512 + tid] = qm; ob[544 + tid] = qm;
        ob[1120 + tid] = pm; ob[1152 + tid] = pm;
    } else if (tid < 64) {
        int j = tid - 32;
        ob[576 + j]  = softp(qs[tid]) + 0.1f;
        ob[1184 + j] = softp(ps[tid]) + 0.1f;
    }

    if (t + 1 < Tv) {
        const int f = is_first[(size_t)b * Tv + t + 1];
        if (tid < 32) x36[tid] = (f > 0) ? g_init[DETERv + tid] : qs[tid];
        else if (tid < 36) x36[tid] = (f > 0) ? 0.f : action[((size_t)b * Tv + t + 1) * ACTv + (tid - 32)];
        __syncthreads();
        prior_in_body(x36, red, b, w_pi, g_pi, bb_pi);
        float* xc = g_xcat + (size_t)b * 1024;
        const float* dsrc = g_deter + (size_t)b * 512;
#pragma unroll
        for (int i = 0; i < 2; i++) {
            int j = tid + 256 * i;
            xc[512 + j] = (f > 0) ? g_init[j] : dsrc[j];
        }
    }
    __syncthreads();
}

// ---------------- persistent kernel ----------------
__global__ __launch_bounds__(256, 2) void k_rssm(
    const float* __restrict__ obs, const float* __restrict__ action,
    const int* __restrict__ is_first,
    const float* __restrict__ w_pi, const float* __restrict__ g_pi, const float* __restrict__ bb_pi,
    const float* __restrict__ w_gru, const float* __restrict__ g_g, const float* __restrict__ bb_g,
    const float* __restrict__ w_po, const float* __restrict__ g_po, const float* __restrict__ bb_po,
    const float* __restrict__ w_ps, const float* __restrict__ b_ps,
    const float* __restrict__ w_post, const float* __restrict__ g_pq, const float* __restrict__ bb_pq,
    const float* __restrict__ w_qs, const float* __restrict__ b_qs,
    const float* __restrict__ init_deter,
    float* __restrict__ out)
{
    __shared__ float sm[6008];
    float* red = sm + 6000;
    const int bid = blockIdx.x;
    const int tid = threadIdx.x;

    if (bid == 0)
        initA_body(sm, red, init_deter, w_po, g_po, bb_po, w_ps, b_ps);
    grid_sync();

    {   // init xcat for t=0 (1 row/CTA)
        float* x36 = sm + 1408;
        const int b = bid;
        const int f = is_first[(size_t)b * Tv];
        if (tid < 32) x36[tid] = g_init[DETERv + tid];
        else if (tid < 36) x36[tid] = (f > 0) ? 0.f : action[(size_t)b * Tv * ACTv + (tid - 32)];
        __syncthreads();
        prior_in_body(x36, red, b, w_pi, g_pi, bb_pi);
        float* xc = g_xcat + (size_t)b * 1024;
#pragma unroll
        for (int i = 0; i < 2; i++) {
            int j = tid + 256 * i;
            xc[512 + j] = g_init[j];
        }
        __syncthreads();
    }
    grid_sync();

    for (int t = 0; t < Tv; t++) {
        gates_body(sm, bid, w_gru);
        grid_sync();

        gru_row_body(red, bid, g_g, bb_g, out, t);
        grid_sync();

        mm_body(sm, bid, w_po, w_post, obs, t);
        grid_sync();

        tail_row_body(sm, red, bid,
                      g_po, bb_po, g_pq, bb_pq,
                      w_ps, b_ps, w_qs, b_qs,
                      w_pi, g_pi, bb_pi,
                      action, is_first, out, t);
        grid_sync();
    }
}

extern "C" void kernel_launch(void* const* d_in, const int* in_sizes, int n_in,
                              void* d_out, int out_size)
{
    const float* obs        = (const float*)d_in[0];
    const float* action     = (const float*)d_in[1];
    const int*   is_first   = (const int*)d_in[2];
    const float* w_prior_in = (const float*)d_in[3];
    const float* g_prior_in = (const float*)d_in[4];
    const float* bb_prior_in= (const float*)d_in[5];
    const float* w_gru      = (const float*)d_in[6];
    const float* g_gru_p    = (const float*)d_in[7];
    const float* bb_gru_p   = (const float*)d_in[8];
    const float* w_prior_out= (const float*)d_in[9];
    const float* g_prior_out= (const float*)d_in[10];
    const float* bb_prior_out=(const float*)d_in[11];
    const float* w_prior_st = (const float*)d_in[12];
    const float* b_prior_st = (const float*)d_in[13];
    const float* w_post     = (const float*)d_in[14];
    const float* g_post     = (const float*)d_in[15];
    const float* bb_post    = (const float*)d_in[16];
    const float* w_post_st  = (const float*)d_in[17];
    const float* b_post_st  = (const float*)d_in[18];
    const float* init_deter = (const float*)d_in[19];
    float* out = (float*)d_out;

    k_rssm<<<NB, 256>>>(obs, action, is_first,
                        w_prior_in, g_prior_in, bb_prior_in,
                        w_gru, g_gru_p, bb_gru_p,
                        w_prior_out, g_prior_out, bb_prior_out,
                        w_prior_st, b_prior_st,
                        w_post, g_post, bb_post,
                        w_post_st, b_post_st,
                        init_deter, out);
}

// round 17
// speedup vs baseline: 1.3376x; 1.0683x over previous
#include <cuda_runtime.h>
#include <math.h>

#define Bv 256
#define Tv 256
#define STOCHv 32
#define DETERv 512
#define HIDv 512
#define OBSv 18
#define ACTv 4
#define GATESv 1536
#define OUTCv 1216
#define NB 256

__device__ float g_xcat[Bv * 1024];        // [b][0:512]=h(t), [512:1024]=deter_in(t)
__device__ float g_gates[8][Bv * GATESv];  // gates split-K partials
__device__ float g_mm[2][8][Bv * HIDv];    // mm split-K partials
__device__ float g_deter[Bv * DETERv];
__device__ float g_init[DETERv + STOCHv];  // deter0, init_mean
__device__ __align__(128) unsigned g_bar_count;
__device__ __align__(128) unsigned g_bar_gen;

typedef unsigned long long u64;

static __device__ __forceinline__ u64 ffma2(u64 a, u64 b, u64 c) {
    u64 d; asm("fma.rn.f32x2 %0, %1, %2, %3;" : "=l"(d) : "l"(a), "l"(b), "l"(c));
    return d;
}
static __device__ __forceinline__ u64 dup2(float x) {
    u64 r; asm("mov.b64 %0, {%1, %1};" : "=l"(r) : "f"(x)); return r;
}
static __device__ __forceinline__ float2 u2f(u64 v) {
    float2 f; asm("mov.b64 {%0, %1}, %2;" : "=f"(f.x), "=f"(f.y) : "l"(v)); return f;
}
static __device__ __forceinline__ float sigm(float x)  { return 1.f / (1.f + expf(-x)); }
static __device__ __forceinline__ float siluf(float x) { return x / (1.f + expf(-x)); }
static __device__ __forceinline__ float softp(float x) { return (x > 20.f) ? x : log1pf(expf(x)); }

// acq/rel grid barrier: no GPU-scope membar. Arrivals use atom.add.acq_rel
// (acquire observes all prior releases; release publishes this CTA's writes).
// The last arriver resets the count and publishes with st.release; spinners
// use ld.acquire, which (with release cumulativity) sees every CTA's writes.
static __device__ __forceinline__ void grid_sync() {
    __syncthreads();
    if (threadIdx.x == 0) {
        unsigned gen;
        asm volatile("ld.relaxed.gpu.u32 %0, [%1];" : "=r"(gen) : "l"(&g_bar_gen) : "memory");
        unsigned prev;
        asm volatile("atom.add.acq_rel.gpu.u32 %0, [%1], 1;"
                     : "=r"(prev) : "l"(&g_bar_count) : "memory");
        if (prev == NB - 1) {
            asm volatile("st.relaxed.gpu.u32 [%0], %1;" :: "l"(&g_bar_count), "r"(0u) : "memory");
            asm volatile("st.release.gpu.u32 [%0], %1;" :: "l"(&g_bar_gen), "r"(gen + 1) : "memory");
        } else {
            unsigned g;
            do {
                asm volatile("ld.acquire.gpu.u32 %0, [%1];" : "=r"(g) : "l"(&g_bar_gen) : "memory");
            } while (g == gen);
        }
    }
    __syncthreads();
}

static __device__ __forceinline__ float block_sum_256(float v, float* red) {
    int lane = threadIdx.x & 31, wid = threadIdx.x >> 5;
#pragma unroll
    for (int o = 16; o; o >>= 1) v += __shfl_xor_sync(0xffffffffu, v, o);
    __syncthreads();
    if (lane == 0) red[wid] = v;
    __syncthreads();
    float s = ((red[0] + red[1]) + (red[2] + red[3]))
            + ((red[4] + red[5]) + (red[6] + red[7]));
    return s;
}

// ---------------- init A (CTA 0) ----------------
static __device__ void initA_body(
    float* sm, float* red,
    const float* __restrict__ initial_deter,
    const float* __restrict__ w_po, const float* __restrict__ g_po, const float* __restrict__ bb_po,
    const float* __restrict__ w_ps, const float* __restrict__ b_ps)
{
    const int tid = threadIdx.x;
    float* d0s = sm;
    float* h0s = sm + 512;
#pragma unroll
    for (int i = 0; i < 2; i++) {
        int j = tid + 256 * i;
        float v = tanhf(initial_deter[j]);
        d0s[j] = v; g_init[j] = v;
    }
    __syncthreads();
    float p[2] = {0.f, 0.f};
    for (int k = 0; k < 512; k++) {
        float dv = d0s[k];
#pragma unroll
        for (int i = 0; i < 2; i++) p[i] += dv * w_po[(size_t)k * 512 + tid + 256 * i];
    }
    float mean = block_sum_256(p[0] + p[1], red) * (1.f / 512.f);
    float e[2], vs = 0.f;
#pragma unroll
    for (int i = 0; i < 2; i++) { e[i] = p[i] - mean; vs += e[i] * e[i]; }
    float var = block_sum_256(vs, red) * (1.f / 512.f);
    float rstd = rsqrtf(var + 1e-3f);
#pragma unroll
    for (int i = 0; i < 2; i++) {
        int j = tid + 256 * i;
        h0s[j] = siluf(e[i] * rstd * g_po[j] + bb_po[j]);
    }
    __syncthreads();
    if (tid < STOCHv) {
        float s0 = 0.f, s1 = 0.f, s2 = 0.f, s3 = 0.f;
        for (int k = 0; k < 512; k += 4) {
            s0 += h0s[k]     * w_ps[(size_t)k * 64 + tid];
            s1 += h0s[k + 1] * w_ps[(size_t)(k + 1) * 64 + tid];
            s2 += h0s[k + 2] * w_ps[(size_t)(k + 2) * 64 + tid];
            s3 += h0s[k + 3] * w_ps[(size_t)(k + 3) * 64 + tid];
        }
        g_init[DETERv + tid] = b_ps[tid] + ((s0 + s1) + (s2 + s3));
    }
    __syncthreads();
}

// prior_in for one row, x36 in smem
static __device__ void prior_in_body(
    float* x36, float* red, int b,
    const float* __restrict__ w_pi, const float* __restrict__ g_pi, const float* __restrict__ bb_pi)
{
    const int tid = threadIdx.x;
    float p[2] = {0.f, 0.f};
#pragma unroll
    for (int k = 0; k < 36; k++) {
        float xv = x36[k];
#pragma unroll
        for (int i = 0; i < 2; i++) p[i] += xv * w_pi[(size_t)k * HIDv + tid + 256 * i];
    }
    float mean = block_sum_256(p[0] + p[1], red) * (1.f / 512.f);
    float e[2], vs = 0.f;
#pragma unroll
    for (int i = 0; i < 2; i++) { e[i] = p[i] - mean; vs += e[i] * e[i]; }
    float var = block_sum_256(vs, red) * (1.f / 512.f);
    float rstd = rsqrtf(var + 1e-3f);
    float* xc = g_xcat + (size_t)b * 1024;
#pragma unroll
    for (int i = 0; i < 2; i++) {
        int j = tid + 256 * i;
        xc[j] = siluf(e[i] * rstd * g_pi[j] + bb_pi[j]);
    }
}

// ---- gates GEMM [256,1024]@[1024,1536]: 2M(128) x 16N(96) x ksplit8(K=128) ----
#define AS_S 132
#define BS_SG 100
static __device__ void gates_body(float* sm, int bid, const float* __restrict__ w_gru)
{
    float* As = sm;           // [16][132]
    float* Bs = sm + 2112;    // [16][100]
    const int tid = threadIdx.x;
    const int row0 = (bid & 1) * 128;
    const int col0 = ((bid >> 1) & 15) * 96;
    const int kz   = bid >> 5;
    const int K0   = kz * 128;
    const int tx = tid & 15, ty = tid >> 4;

    u64 acc[4][6];
#pragma unroll
    for (int p = 0; p < 4; p++)
#pragma unroll
        for (int c = 0; c < 6; c++) acc[p][c] = 0ull;

    const int ar = tid >> 1, akg = (tid & 1) * 8;
    const float* Ap = g_xcat + (size_t)(row0 + ar) * 1024 + K0 + akg;
    const int bk0 = tid / 24,         bn0 = (tid % 24) * 4;
    const bool hasB1 = (tid < 128);
    const int bk1 = (tid + 256) / 24, bn1 = ((tid + 256) % 24) * 4;
    const float* Bp0 = w_gru + (size_t)(K0 + bk0) * GATESv + col0 + bn0;
    const float* Bp1 = w_gru + (size_t)(K0 + bk1) * GATESv + col0 + bn1;

    float4 a0 = *(const float4*)Ap;
    float4 a1 = *(const float4*)(Ap + 4);
    float4 b0 = *(const float4*)Bp0;
    float4 b1 = hasB1 ? *(const float4*)Bp1 : make_float4(0.f, 0.f, 0.f, 0.f);

    for (int kt = 0; kt < 8; kt++) {
        {
            float v[8] = {a0.x, a0.y, a0.z, a0.w, a1.x, a1.y, a1.z, a1.w};
#pragma unroll
            for (int j = 0; j < 8; j++) As[(akg + j) * AS_S + ar] = v[j];
        }
        *(float4*)&Bs[bk0 * BS_SG + bn0] = b0;
        if (hasB1) *(float4*)&Bs[bk1 * BS_SG + bn1] = b1;
        __syncthreads();
        if (kt + 1 < 8) {
            a0 = *(const float4*)(Ap + (size_t)(kt + 1) * 16);
            a1 = *(const float4*)(Ap + (size_t)(kt + 1) * 16 + 4);
            b0 = *(const float4*)(Bp0 + (size_t)(kt + 1) * 16 * GATESv);
            if (hasB1) b1 = *(const float4*)(Bp1 + (size_t)(kt + 1) * 16 * GATESv);
        }
#pragma unroll 4
        for (int k = 0; k < 16; k++) {
            const u64* app = (const u64*)(As + k * AS_S + ty * 8);
            u64 ap0 = app[0], ap1 = app[1], ap2 = app[2], ap3 = app[3];
            const float* Bc = Bs + k * BS_SG + 2 * tx;
#pragma unroll
            for (int q = 0; q < 3; q++) {
                float2 bq = *(const float2*)(Bc + 32 * q);
                u64 d0 = dup2(bq.x), d1 = dup2(bq.y);
                acc[0][2 * q]     = ffma2(ap0, d0, acc[0][2 * q]);
                acc[0][2 * q + 1] = ffma2(ap0, d1, acc[0][2 * q + 1]);
                acc[1][2 * q]     = ffma2(ap1, d0, acc[1][2 * q]);
                acc[1][2 * q + 1] = ffma2(ap1, d1, acc[1][2 * q + 1]);
                acc[2][2 * q]     = ffma2(ap2, d0, acc[2][2 * q]);
                acc[2][2 * q + 1] = ffma2(ap2, d1, acc[2][2 * q + 1]);
                acc[3][2 * q]     = ffma2(ap3, d0, acc[3][2 * q]);
                acc[3][2 * q + 1] = ffma2(ap3, d1, acc[3][2 * q + 1]);
            }
        }
        __syncthreads();
    }
    float* G = g_gates[kz];
#pragma unroll
    for (int p = 0; p < 4; p++) {
        float2 c0v = u2f(acc[p][0]), c1v = u2f(acc[p][1]);
        float2 c2v = u2f(acc[p][2]), c3v = u2f(acc[p][3]);
        float2 c4v = u2f(acc[p][4]), c5v = u2f(acc[p][5]);
        size_t rA = (size_t)(row0 + ty * 8 + 2 * p) * GATESv + col0 + 2 * tx;
        size_t rB = rA + GATESv;
        *(float2*)&G[rA]      = make_float2(c0v.x, c1v.x);
        *(float2*)&G[rA + 32] = make_float2(c2v.x, c3v.x);
        *(float2*)&G[rA + 64] = make_float2(c4v.x, c5v.x);
        *(float2*)&G[rB]      = make_float2(c0v.y, c1v.y);
        *(float2*)&G[rB + 32] = make_float2(c2v.y, c3v.y);
        *(float2*)&G[rB + 64] = make_float2(c4v.y, c5v.y);
    }
}

// ---- GRU for row b (1 row/CTA): smem-free, float2 loads ----
static __device__ void gru_row_body(
    float* red, int b,
    const float* __restrict__ g_g, const float* __restrict__ bb_g,
    float* __restrict__ out, int t)
{
    const int tid = threadIdx.x;
    const int j2 = 2 * tid;
    float2 vv[3];
    float s = 0.f;
#pragma unroll
    for (int i = 0; i < 3; i++) {
        float ax = 0.f, ay = 0.f;
#pragma unroll
        for (int kz = 0; kz < 8; kz++) {
            float2 v = ((const float2*)(g_gates[kz] + (size_t)b * GATESv))[tid + 256 * i];
            ax += v.x; ay += v.y;
        }
        vv[i] = make_float2(ax, ay);
        s += ax + ay;
    }
    float mean = block_sum_256(s, red) * (1.f / 1536.f);
    float vs = 0.f;
#pragma unroll
    for (int i = 0; i < 3; i++) {
        float e0 = vv[i].x - mean, e1 = vv[i].y - mean;
        vs += e0 * e0 + e1 * e1;
    }
    float var = block_sum_256(vs, red) * (1.f / 1536.f);
    float rstd = rsqrtf(var + 1e-3f);

    float2 ggr = *(const float2*)&g_g[j2];
    float2 ggc = *(const float2*)&g_g[j2 + 512];
    float2 ggu = *(const float2*)&g_g[j2 + 1024];
    float2 gbr = *(const float2*)&bb_g[j2];
    float2 gbc = *(const float2*)&bb_g[j2 + 512];
    float2 gbu = *(const float2*)&bb_g[j2 + 1024];
    float2 xv  = *(const float2*)(g_xcat + (size_t)b * 1024 + 512 + j2);

    float r0 = sigm((vv[0].x - mean) * rstd * ggr.x + gbr.x);
    float r1 = sigm((vv[0].y - mean) * rstd * ggr.y + gbr.y);
    float c0 = (vv[1].x - mean) * rstd * ggc.x + gbc.x;
    float c1 = (vv[1].y - mean) * rstd * ggc.y + gbc.y;
    float u0 = sigm((vv[2].x - mean) * rstd * ggu.x + gbu.x - 1.0f);
    float u1 = sigm((vv[2].y - mean) * rstd * ggu.y + gbu.y - 1.0f);
    float d0 = u0 * siluf(r0 * c0) + (1.f - u0) * xv.x;
    float d1 = u1 * siluf(r1 * c1) + (1.f - u1) * xv.y;

    float2 dd = make_float2(d0, d1);
    *(float2*)(g_deter + (size_t)b * 512 + j2) = dd;
    float* ob = out + ((size_t)b * Tv + t) * OUTCv;
    *(float2*)&ob[j2] = dd;
    *(float2*)&ob[608 + j2] = dd;
}

// ---- mm GEMMs: 2M(128) x 8N(64) x 2z x ksplit8(K=64); UNIFORM (obs in tail) ----
#define BS_SM 68
static __device__ void mm_body(
    float* sm, int bid,
    const float* __restrict__ w_po, const float* __restrict__ w_post)
{
    float* As = sm;           // [16][132]
    float* Bs = sm + 2112;    // [16][68]
    const int tid = threadIdx.x;
    const int m2 = bid & 1;
    const int c0 = ((bid >> 1) & 7) * 64;
    const int z  = (bid >> 4) & 1;
    const int kz = bid >> 5;
    const int K0 = kz * 64;
    const int tx = tid & 15, ty = tid >> 4;
    const float* W = z ? w_post : w_po;

    u64 acc[4][4];
#pragma unroll
    for (int p = 0; p < 4; p++)
#pragma unroll
        for (int c = 0; c < 4; c++) acc[p][c] = 0ull;

    const int ar = tid >> 1, akg = (tid & 1) * 8;
    const float* Ap = g_deter + (size_t)(m2 * 128 + ar) * 512 + K0 + akg;
    const int bk = tid >> 4, bn = (tid & 15) * 4;
    const float* Bp = W + (size_t)(K0 + bk) * 512 + c0 + bn;

    float4 a0 = *(const float4*)Ap;
    float4 a1 = *(const float4*)(Ap + 4);
    float4 b0 = *(const float4*)Bp;

    for (int kt = 0; kt < 4; kt++) {
        {
            float v[8] = {a0.x, a0.y, a0.z, a0.w, a1.x, a1.y, a1.z, a1.w};
#pragma unroll
            for (int j = 0; j < 8; j++) As[(akg + j) * AS_S + ar] = v[j];
        }
        *(float4*)&Bs[bk * BS_SM + bn] = b0;
        __syncthreads();
        if (kt + 1 < 4) {
            a0 = *(const float4*)(Ap + (size_t)(kt + 1) * 16);
            a1 = *(const float4*)(Ap + (size_t)(kt + 1) * 16 + 4);
            b0 = *(const float4*)(Bp + (size_t)(kt + 1) * 16 * 512);
        }
#pragma unroll 4
        for (int k = 0; k < 16; k++) {
            const u64* app = (const u64*)(As + k * AS_S + ty * 8);
            u64 ap0 = app[0], ap1 = app[1], ap2 = app[2], ap3 = app[3];
            const float* Bc = Bs + k * BS_SM + 2 * tx;
#pragma unroll
            for (int q = 0; q < 2; q++) {
                float2 bq = *(const float2*)(Bc + 32 * q);
                u64 d0 = dup2(bq.x), d1 = dup2(bq.y);
                acc[0][2 * q]     = ffma2(ap0, d0, acc[0][2 * q]);
                acc[0][2 * q + 1] = ffma2(ap0, d1, acc[0][2 * q + 1]);
                acc[1][2 * q]     = ffma2(ap1, d0, acc[1][2 * q]);
                acc[1][2 * q + 1] = ffma2(ap1, d1, acc[1][2 * q + 1]);
                acc[2][2 * q]     = ffma2(ap2, d0, acc[2][2 * q]);
                acc[2][2 * q + 1] = ffma2(ap2, d1, acc[2][2 * q + 1]);
                acc[3][2 * q]     = ffma2(ap3, d0, acc[3][2 * q]);
                acc[3][2 * q + 1] = ffma2(ap3, d1, acc[3][2 * q + 1]);
            }
        }
        __syncthreads();
    }

    float* Gm = g_mm[z][kz];
#pragma unroll
    for (int p = 0; p < 4; p++) {
        float2 c0v = u2f(acc[p][0]), c1v = u2f(acc[p][1]);
        float2 c2v = u2f(acc[p][2]), c3v = u2f(acc[p][3]);
        size_t rA = (size_t)(m2 * 128 + ty * 8 + 2 * p) * 512 + c0 + 2 * tx;
        size_t rB = rA + 512;
        *(float2*)&Gm[rA]      = make_float2(c0v.x, c1v.x);
        *(float2*)&Gm[rA + 32] = make_float2(c2v.x, c3v.x);
        *(float2*)&Gm[rB]      = make_float2(c0v.y, c1v.y);
        *(float2*)&Gm[rB + 32] = make_float2(c2v.y, c3v.y);
    }
}

// ---- tail for row b (1 row/CTA): float2 reduce (+obs term), 8-acc stats GEMV ----
static __device__ void tail_row_body(
    float* sm, float* red, int b,
    const float* __restrict__ g_po, const float* __restrict__ bb_po,
    const float* __restrict__ g_pq, const float* __restrict__ bb_pq,
    const float* __restrict__ w_ps, const float* __restrict__ b_ps,
    const float* __restrict__ w_qs, const float* __restrict__ b_qs,
    const float* __restrict__ w_pi, const float* __restrict__ g_pi, const float* __restrict__ bb_pi,
    const float* __restrict__ w_post, const float* __restrict__ obs,
    const float* __restrict__ action, const int* __restrict__ is_first,
    float* __restrict__ out, int t)
{
    const int tid = threadIdx.x;
    const int j2 = 2 * tid;
    float* h2    = sm;           // 512
    float* h3    = sm + 512;     // 512
    float* ps    = sm + 1024;    // 64
    float* qs    = sm + 1088;    // 64
    float* pp    = sm + 1152;    // 256
    float* x36   = sm + 1408;    // 40
    float* obs_s = sm + 1456;    // 18

    if (tid < OBSv) obs_s[tid] = obs[((size_t)b * Tv + t) * OBSv + tid];
    // the z=0 block_sum's __syncthreads orders obs_s before its z=1 read

#pragma unroll
    for (int z = 0; z < 2; z++) {
        float ax = 0.f, ay = 0.f;
#pragma unroll
        for (int kzi = 0; kzi < 8; kzi++) {
            float2 v = ((const float2*)(g_mm[z][kzi] + (size_t)b * 512))[tid];
            ax += v.x; ay += v.y;
        }
        if (z == 1) {  // obs contribution to post pre-LN (K rows 512..529)
#pragma unroll
            for (int k = 0; k < OBSv; k++) {
                float ov = obs_s[k];
                float2 w2 = *(const float2*)&w_post[(size_t)(512 + k) * 512 + j2];
                ax += ov * w2.x; ay += ov * w2.y;
            }
        }
        float mean = block_sum_256(ax + ay, red) * (1.f / 512.f);
        float e0 = ax - mean, e1 = ay - mean;
        float var = block_sum_256(e0 * e0 + e1 * e1, red) * (1.f / 512.f);
        float rstd = rsqrtf(var + 1e-3f);
        const float* gg = z ? g_pq : g_po;
        const float* gb = z ? bb_pq : bb_po;
        float2 gg2 = *(const float2*)&gg[j2];
        float2 gb2 = *(const float2*)&gb[j2];
        float* hv = z ? h3 : h2;
        hv[j2]     = siluf(e0 * rstd * gg2.x + gb2.x);
        hv[j2 + 1] = siluf(e1 * rstd * gg2.y + gb2.y);
    }
    __syncthreads();

    // stats GEMVs: 128 outputs, split-K across thread halves, 8-way MLP
    {
        const int half = tid >> 7;
        const int tl   = tid & 127;
        const int j    = tl & 63;
        const float* hv = (tl < 64) ? h2 : h3;
        const float* W  = (tl < 64) ? w_ps : w_qs;
        const int kbase = half * 256;
        float s[8];
#pragma unroll
        for (int u = 0; u < 8; u++) s[u] = 0.f;
#pragma unroll 2
        for (int k = 0; k < 256; k += 8) {
#pragma unroll
            for (int u = 0; u < 8; u++) {
                int kk = kbase + k + u;
                s[u] += hv[kk] * W[(size_t)kk * 64 + j];
            }
        }
        pp[tid] = ((s[0] + s[1]) + (s[2] + s[3])) + ((s[4] + s[5]) + (s[6] + s[7]));
    }
    __syncthreads();
    if (tid < 128) {
        const int j = tid & 63;
        float s = (pp[tid] + pp[tid + 128]) + ((tid < 64) ? b_ps[j] : b_qs[j]);
        if (tid < 64) ps[j] = s; else qs[j] = s;
    }
    __syncthreads();

    float* ob = out + ((size_t)b * Tv + t) * OUTCv;
    if (tid < 32) {
        float qm = qs[tid], pm = ps[tid];
        ob[512 + tid] = qm; ob[544 + tid] = qm;
        ob[1120 + tid] = pm; ob[1152 + tid] = pm;
    } else if (tid < 64) {
        int j = tid - 32;
        ob[576 + j]  = softp(qs[tid]) + 0.1f;
        ob[1184 + j] = softp(ps[tid]) + 0.1f;
    }

    if (t + 1 < Tv) {
        const int f = is_first[(size_t)b * Tv + t + 1];
        if (tid < 32) x36[tid] = (f > 0) ? g_init[DETERv + tid] : qs[tid];
        else if (tid < 36) x36[tid] = (f > 0) ? 0.f : action[((size_t)b * Tv + t + 1) * ACTv + (tid - 32)];
        __syncthreads();
        prior_in_body(x36, red, b, w_pi, g_pi, bb_pi);
        float* xc = g_xcat + (size_t)b * 1024;
        const float* dsrc = g_deter + (size_t)b * 512;
#pragma unroll
        for (int i = 0; i < 2; i++) {
            int j = tid + 256 * i;
            xc[512 + j] = (f > 0) ? g_init[j] : dsrc[j];
        }
    }
    __syncthreads();
}

// ---------------- persistent kernel ----------------
__global__ __launch_bounds__(256, 2) void k_rssm(
    const float* __restrict__ obs, const float* __restrict__ action,
    const int* __restrict__ is_first,
    const float* __restrict__ w_pi, const float* __restrict__ g_pi, const float* __restrict__ bb_pi,
    const float* __restrict__ w_gru, const float* __restrict__ g_g, const float* __restrict__ bb_g,
    const float* __restrict__ w_po, const float* __restrict__ g_po, const float* __restrict__ bb_po,
    const float* __restrict__ w_ps, const float* __restrict__ b_ps,
    const float* __restrict__ w_post, const float* __restrict__ g_pq, const float* __restrict__ bb_pq,
    const float* __restrict__ w_qs, const float* __restrict__ b_qs,
    const float* __restrict__ init_deter,
    float* __restrict__ out)
{
    __shared__ float sm[6008];
    float* red = sm + 6000;
    const int bid = blockIdx.x;
    const int tid = threadIdx.x;

    if (bid == 0)
        initA_body(sm, red, init_deter, w_po, g_po, bb_po, w_ps, b_ps);
    grid_sync();

    {   // init xcat for t=0 (1 row/CTA)
        float* x36 = sm + 1408;
        const int b = bid;
        const int f = is_first[(size_t)b * Tv];
        if (tid < 32) x36[tid] = g_init[DETERv + tid];
        else if (tid < 36) x36[tid] = (f > 0) ? 0.f : action[(size_t)b * Tv * ACTv + (tid - 32)];
        __syncthreads();
        prior_in_body(x36, red, b, w_pi, g_pi, bb_pi);
        float* xc = g_xcat + (size_t)b * 1024;
#pragma unroll
        for (int i = 0; i < 2; i++) {
            int j = tid + 256 * i;
            xc[512 + j] = g_init[j];
        }
        __syncthreads();
    }
    grid_sync();

    for (int t = 0; t < Tv; t++) {
        gates_body(sm, bid, w_gru);
        grid_sync();

        gru_row_body(red, bid, g_g, bb_g, out, t);
        grid_sync();

        mm_body(sm, bid, w_po, w_post);
        grid_sync();

        tail_row_body(sm, red, bid,
                      g_po, bb_po, g_pq, bb_pq,
                      w_ps, b_ps, w_qs, b_qs,
                      w_pi, g_pi, bb_pi,
                      w_post, obs,
                      action, is_first, out, t);
        grid_sync();
    }
}

extern "C" void kernel_launch(void* const* d_in, const int* in_sizes, int n_in,
                              void* d_out, int out_size)
{
    const float* obs        = (const float*)d_in[0];
    const float* action     = (const float*)d_in[1];
    const int*   is_first   = (const int*)d_in[2];
    const float* w_prior_in = (const float*)d_in[3];
    const float* g_prior_in = (const float*)d_in[4];
    const float* bb_prior_in= (const float*)d_in[5];
    const float* w_gru      = (const float*)d_in[6];
    const float* g_gru_p    = (const float*)d_in[7];
    const float* bb_gru_p   = (const float*)d_in[8];
    const float* w_prior_out= (const float*)d_in[9];
    const float* g_prior_out= (const float*)d_in[10];
    const float* bb_prior_out=(const float*)d_in[11];
    const float* w_prior_st = (const float*)d_in[12];
    const float* b_prior_st = (const float*)d_in[13];
    const float* w_post     = (const float*)d_in[14];
    const float* g_post     = (const float*)d_in[15];
    const float* bb_post    = (const float*)d_in[16];
    const float* w_post_st  = (const float*)d_in[17];
    const float* b_post_st  = (const float*)d_in[18];
    const float* init_deter = (const float*)d_in[19];
    float* out = (float*)d_out;

    k_rssm<<<NB, 256>>>(obs, action, is_first,
                        w_prior_in, g_prior_in, bb_prior_in,
                        w_gru, g_gru_p, bb_gru_p,
                        w_prior_out, g_prior_out, bb_prior_out,
                        w_prior_st, b_prior_st,
                        w_post, g_post, bb_post,
                        w_post_st, b_post_st,
                        init_deter, out);
}